// round 15
// baseline (speedup 1.0000x reference)
#include <cuda_runtime.h>
#include <math.h>
#include <stdint.h>

#define NSEQ   1024
#define XDIM   2048
#define NHEADS 16
#define KVH    2
#define GQH    8
#define DH     128
#define QKVW   2560      // 2048 + 256 + 256
#define CDIM   4096      // CMP_BLK * DH
#define SCALE  0.08838834764831845f
#define NEGBIG -1e10f

// ---------------- scratch (device globals; no runtime allocation) ----------------
__device__ __align__(128) float g_xn    [NSEQ*XDIM];
__device__ __align__(128) float g_qkv   [NSEQ*QKVW];
__device__ __align__(128) float g_hidden[2*128*CDIM];
__device__ __align__(128) float g_ckfull[KVH*65*DH];
__device__ __align__(128) float g_cvfull[KVH*65*DH];
__device__ __align__(128) float g_cmp   [NHEADS*NSEQ*DH];
__device__ __align__(128) float g_fine  [NHEADS*NSEQ*DH];
__device__ __align__(128) float g_slide [NHEADS*NSEQ*DH];
__device__ __align__(128) float g_qrope [NHEADS*NSEQ*DH];
__device__ __align__(128) float g_krope [KVH*NSEQ*DH];
__device__ __align__(128) float g_ropetab[NSEQ*64*2];
__device__ __align__(128) float g_gpart [16*NSEQ*48];
__device__ int g_sel[KVH*NSEQ*5];

// fragment-layout operand buffers
__device__ float4 g_BFq [256*320*32];       // W_qkv (split)
__device__ float2 g_BFo [256*256*32];       // W_out (plain)
__device__ float4 g_AXh[256*64*32],  g_AXl[256*64*32];    // xn
__device__ float4 g_AFh[2*512*8*32], g_AFl[2*512*8*32];   // compress-MLP inputs
__device__ float4 g_AOh[256*64*32];                       // combined O1 (hi only)

// ---------------- helpers ----------------
__device__ __forceinline__ float warp_sum(float v){
    #pragma unroll
    for (int o = 16; o > 0; o >>= 1) v += __shfl_xor_sync(0xffffffffu, v, o);
    return v;
}
__device__ __forceinline__ float warp_max(float v){
    #pragma unroll
    for (int o = 16; o > 0; o >>= 1) v = fmaxf(v, __shfl_xor_sync(0xffffffffu, v, o));
    return v;
}
__device__ __forceinline__ float tf32r(float x){
    unsigned r; asm("cvt.rna.tf32.f32 %0, %1;" : "=r"(r) : "f"(x));
    return __uint_as_float(r);
}
__device__ __forceinline__ void mma8(float* d, const unsigned* a, const unsigned* b){
    asm volatile("mma.sync.aligned.m16n8k8.row.col.f32.tf32.tf32.f32 "
        "{%0,%1,%2,%3},{%4,%5,%6,%7},{%8,%9},{%0,%1,%2,%3};"
        : "+f"(d[0]),"+f"(d[1]),"+f"(d[2]),"+f"(d[3])
        : "r"(a[0]),"r"(a[1]),"r"(a[2]),"r"(a[3]),"r"(b[0]),"r"(b[1]));
}
__device__ __forceinline__ void cp16(uint32_t s, const void* g){
    asm volatile("cp.async.cg.shared.global [%0], [%1], 16;" :: "r"(s), "l"(g));
}
__device__ __forceinline__ void cp8(uint32_t s, const void* g){
    asm volatile("cp.async.ca.shared.global [%0], [%1], 8;" :: "r"(s), "l"(g));
}
__device__ __forceinline__ void afrag_store(float* ph, float* pl, int M16,
                                            int row, int k, float v){
    int ks = k >> 3, mt = row >> 4;
    int lane = (row & 7)*4 + (k & 3);
    int slot = ((row >> 3) & 1) + 2*((k >> 2) & 1);
    size_t fi = (((size_t)ks*M16 + mt)*32 + lane)*4 + slot;
    float h = tf32r(v);
    ph[fi] = h;
    pl[fi] = tf32r(v - h);
}

// ---------------- weight prep bodies ----------------
__device__ __forceinline__ void prep4_body(const float* __restrict__ W,
                                           float4* __restrict__ BF, int N,
                                           int bx, int by, float (*sw)[65]){
    int n0 = bx*64, k0 = by*64;
    int t = threadIdx.x;
    #pragma unroll
    for (int ii = 0; ii < 4; ii++){
        int r = ii*16 + (t >> 4), c4 = (t & 15)*4;
        float4 v = *(const float4*)(W + (size_t)(k0 + r)*N + n0 + c4);
        sw[r][c4+0]=v.x; sw[r][c4+1]=v.y; sw[r][c4+2]=v.z; sw[r][c4+3]=v.w;
    }
    __syncthreads();
    int lane = t & 31, ct = t >> 5;
    int c = lane & 3, gcol = lane >> 2;
    #pragma unroll
    for (int i = 0; i < 8; i++){
        float v1 = sw[i*8 + c][ct*8 + gcol];
        float v2 = sw[i*8 + 4 + c][ct*8 + gcol];
        float h1 = tf32r(v1), l1 = tf32r(v1 - h1);
        float h2 = tf32r(v2), l2 = tf32r(v2 - h2);
        BF[((size_t)(k0/8 + i)*(N >> 3) + (n0 >> 3) + ct)*32 + lane] =
            make_float4(h1, h2, l1, l2);
    }
}
__device__ __forceinline__ void prep2_body(const float* __restrict__ W,
                                           float2* __restrict__ BF, int N,
                                           int bx, int by, float (*sw)[65]){
    int n0 = bx*64, k0 = by*64;
    int t = threadIdx.x;
    #pragma unroll
    for (int ii = 0; ii < 4; ii++){
        int r = ii*16 + (t >> 4), c4 = (t & 15)*4;
        float4 v = *(const float4*)(W + (size_t)(k0 + r)*N + n0 + c4);
        sw[r][c4+0]=v.x; sw[r][c4+1]=v.y; sw[r][c4+2]=v.z; sw[r][c4+3]=v.w;
    }
    __syncthreads();
    int lane = t & 31, ct = t >> 5;
    int c = lane & 3, gcol = lane >> 2;
    #pragma unroll
    for (int i = 0; i < 8; i++){
        float v1 = sw[i*8 + c][ct*8 + gcol];
        float v2 = sw[i*8 + 4 + c][ct*8 + gcol];
        BF[((size_t)(k0/8 + i)*(N >> 3) + (n0 >> 3) + ct)*32 + lane] =
            make_float2(tf32r(v1), tf32r(v2));
    }
}

// ---------------- fused stage0: rmsnorm + weight preps + rope table ----------
__global__ void stage0_kernel(const float* __restrict__ x, const float* __restrict__ g,
                              const float* __restrict__ Wq, const float* __restrict__ Wo){
    __shared__ float sw[64][65];
    int id = blockIdx.x;
    int tid = threadIdx.x;
    if (id < 1024){
        int n = id;
        const float4* row = (const float4*)(x + (size_t)n*XDIM);
        float s = 0.f;
        for (int i = tid; i < XDIM/4; i += 256){
            float4 v = row[i];
            s += v.x*v.x + v.y*v.y + v.z*v.z + v.w*v.w;
        }
        s = warp_sum(s);
        __shared__ float red[8];
        __shared__ float tot;
        if ((tid & 31) == 0) red[tid >> 5] = s;
        __syncthreads();
        if (tid < 32){
            float v = (tid < 8) ? red[tid] : 0.f;
            v = warp_sum(v);
            if (tid == 0) tot = rsqrtf(v / (float)XDIM + 1e-6f);
        }
        __syncthreads();
        float inv = tot;
        const float4* gg = (const float4*)g;
        float4* op = (float4*)(g_xn + (size_t)n*XDIM);
        float* ph = (float*)g_AXh;
        float* pl = (float*)g_AXl;
        for (int i = tid; i < XDIM/4; i += 256){
            float4 v = row[i], w = gg[i], o;
            o.x = v.x*inv*w.x; o.y = v.y*inv*w.y; o.z = v.z*inv*w.z; o.w = v.w*inv*w.w;
            op[i] = o;
            int k0 = i*4;
            afrag_store(ph, pl, 64, n, k0+0, o.x);
            afrag_store(ph, pl, 64, n, k0+1, o.y);
            afrag_store(ph, pl, 64, n, k0+2, o.z);
            afrag_store(ph, pl, 64, n, k0+3, o.w);
        }
        return;
    }
    id -= 1024;
    if (id < 1280){ prep4_body(Wq, g_BFq, QKVW, id % 40, id / 40, sw); return; }
    id -= 1280;
    if (id < 1024){ prep2_body(Wo, g_BFo, XDIM, id % 32, id / 32, sw); return; }
    id -= 1024;
    int idx = id * 256 + tid;
    int i = idx & 63, n = idx >> 6;
    double f = exp(-((double)(2*i) / 128.0) * 9.210340371976184);
    double ang = (double)n * f;
    g_ropetab[idx*2 + 0] = (float)cos(ang);
    g_ropetab[idx*2 + 1] = (float)sin(ang);
}

// ---------------- tensor-core GEMM (prepped B frags in gmem) ----------------
template<bool SPLIT>
__global__ __launch_bounds__(256)
void gemm_tc(const float4* __restrict__ AFh, const float4* __restrict__ AFl,
             const void* __restrict__ BFv,
             const float* __restrict__ bias,
             float* __restrict__ C,
             int M16, int N, int K, int relu){
    constexpr int MT16 = 8;
    constexpr int NT = 4;
    constexpr int APS = SPLIT ? 2 : 1;
    constexpr int SA_F4 = APS*4*MT16*32;
    constexpr int SB_EL = 4*8*32;

    extern __shared__ float4 smem[];
    char* sBraw = (char*)(smem + 2*SA_F4);

    int tid = threadIdx.x, lane = tid & 31, warp = tid >> 5;
    int bm16 = blockIdx.y*MT16;
    int bn8  = blockIdx.x*8;
    int wmi = warp & 3, wni = warp >> 2;
    int gid = lane >> 2, tig = lane & 3;
    int N8 = N >> 3;

    uint32_t sbase = (uint32_t)__cvta_generic_to_shared(smem);
    uint32_t sbB   = (uint32_t)__cvta_generic_to_shared(sBraw);

    float acc[2][NT][4];
    #pragma unroll
    for (int i = 0; i < 2; i++)
        #pragma unroll
        for (int j = 0; j < NT; j++)
            #pragma unroll
            for (int e = 0; e < 4; e++) acc[i][j][e] = 0.f;

    auto issue = [&](int ksl, int buf){
        #pragma unroll
        for (int i = 0; i < APS*4*MT16*32/256; i++){
            int idx = i*256 + tid;
            int l = idx & 31, q = idx >> 5;
            int mt = q % MT16, ks = (q/MT16) & 3, a = q/(MT16*4);
            const float4* src = (SPLIT && a ? AFl : AFh)
                + ((size_t)(ksl*4 + ks)*M16 + bm16 + mt)*32 + l;
            uint32_t dst = sbase + (uint32_t)(buf*SA_F4 + ((a*4+ks)*MT16+mt)*32+l)*16u;
            cp16(dst, src);
        }
        #pragma unroll
        for (int i = 0; i < 4; i++){
            int idx = i*256 + tid;
            int l = idx & 31, ct = (idx >> 5) & 7, ks = idx >> 8;
            size_t si = ((size_t)(ksl*4 + ks)*N8 + bn8 + ct)*32 + l;
            uint32_t dst = sbB + (uint32_t)(buf*SB_EL + (ks*8+ct)*32 + l)*(SPLIT?16u:8u);
            if (SPLIT) cp16(dst, (const float4*)BFv + si);
            else       cp8 (dst, (const float2*)BFv + si);
        }
        asm volatile("cp.async.commit_group;");
    };

    int nslab = K/32;
    issue(0, 0);
    int buf = 0;
    for (int ksl = 0; ksl < nslab; ksl++){
        asm volatile("cp.async.wait_group 0;");
        __syncthreads();
        if (ksl + 1 < nslab) issue(ksl + 1, buf ^ 1);
        #pragma unroll
        for (int ks = 0; ks < 4; ks++){
            uint4 ah[2], al[2];
            #pragma unroll
            for (int mt = 0; mt < 2; mt++){
                int mtt = wmi*2 + mt;
                ah[mt] = *(const uint4*)&smem[buf*SA_F4 + ((0*4+ks)*MT16+mtt)*32 + lane];
                if (SPLIT)
                    al[mt] = *(const uint4*)&smem[buf*SA_F4 + ((1*4+ks)*MT16+mtt)*32 + lane];
            }
            #pragma unroll
            for (int nt = 0; nt < NT; nt++){
                int bi = (ks*8 + wni*NT + nt)*32 + lane;
                unsigned bh[2], bl[2];
                if (SPLIT){
                    float4 bf = ((const float4*)sBraw)[buf*SB_EL + bi];
                    bh[0]=__float_as_uint(bf.x); bh[1]=__float_as_uint(bf.y);
                    bl[0]=__float_as_uint(bf.z); bl[1]=__float_as_uint(bf.w);
                } else {
                    float2 bf = ((const float2*)sBraw)[buf*SB_EL + bi];
                    bh[0]=__float_as_uint(bf.x); bh[1]=__float_as_uint(bf.y);
                }
                #pragma unroll
                for (int mt = 0; mt < 2; mt++){
                    if (SPLIT){
                        mma8(acc[mt][nt], (const unsigned*)&ah[mt], bl);
                        mma8(acc[mt][nt], (const unsigned*)&al[mt], bh);
                    }
                    mma8(acc[mt][nt], (const unsigned*)&ah[mt], bh);
                }
            }
        }
        buf ^= 1;
    }

    #pragma unroll
    for (int mt = 0; mt < 2; mt++){
        int row = (bm16 + wmi*2 + mt)*16 + gid;
        #pragma unroll
        for (int nt = 0; nt < NT; nt++){
            int col = (bn8 + wni*NT + nt)*8 + tig*2;
            float b0 = bias ? bias[col]   : 0.f;
            float b1 = bias ? bias[col+1] : 0.f;
            float d0 = acc[mt][nt][0] + b0, d1 = acc[mt][nt][1] + b1;
            float d2 = acc[mt][nt][2] + b0, d3 = acc[mt][nt][3] + b1;
            if (relu){
                d0 = fmaxf(d0, 0.f); d1 = fmaxf(d1, 0.f);
                d2 = fmaxf(d2, 0.f); d3 = fmaxf(d3, 0.f);
            }
            *(float2*)(C + (size_t)row*N + col)     = make_float2(d0, d1);
            *(float2*)(C + (size_t)(row+8)*N + col) = make_float2(d2, d3);
        }
    }
}

// ---------------- MLP1 GEMM: BM=64, raw B weights, in-kernel split conversion --
__global__ __launch_bounds__(256)
void gemm_mlp1(const float* __restrict__ Wk1, const float* __restrict__ Wv1,
               const float* __restrict__ bk1, const float* __restrict__ bv1){
    constexpr int NT = 2;
    constexpr int SA_F4 = 2*4*4*32;
    extern __shared__ float4 smem[];
    float* sRaw  = (float*)(smem + 2*SA_F4);
    float4* sBF  = (float4*)(sRaw + 2*32*64);

    const float* W    = blockIdx.z ? Wv1 : Wk1;
    const float* bias = blockIdx.z ? bv1 : bk1;
    const float4* AFh = g_AFh + (size_t)blockIdx.z*512*8*32;
    const float4* AFl = g_AFl + (size_t)blockIdx.z*512*8*32;
    float* C = g_hidden + (size_t)blockIdx.z*128*CDIM;

    int tid = threadIdx.x, lane = tid & 31, warp = tid >> 5;
    int bn = blockIdx.x*64;
    int bm16 = blockIdx.y*4;
    int wmi = warp & 1, wni = warp >> 1;
    int gid = lane >> 2, tig = lane & 3;

    uint32_t sbase = (uint32_t)__cvta_generic_to_shared(smem);
    uint32_t sbRaw = (uint32_t)__cvta_generic_to_shared(sRaw);

    float acc[2][NT][4];
    #pragma unroll
    for (int i = 0; i < 2; i++)
        #pragma unroll
        for (int j = 0; j < NT; j++)
            #pragma unroll
            for (int e = 0; e < 4; e++) acc[i][j][e] = 0.f;

    auto issue = [&](int ksl, int buf){
        #pragma unroll
        for (int i = 0; i < 4; i++){
            int idx = i*256 + tid;
            int l = idx & 31, q = idx >> 5;
            int mt = q & 3, ks = (q >> 2) & 3, a = q >> 4;
            const float4* src = (a ? AFl : AFh)
                + ((size_t)(ksl*4 + ks)*8 + bm16 + mt)*32 + l;
            uint32_t dst = sbase + (uint32_t)(buf*SA_F4 + ((a*4+ks)*4+mt)*32+l)*16u;
            cp16(dst, src);
        }
        #pragma unroll
        for (int i = 0; i < 2; i++){
            int idx = i*256 + tid;
            int k = idx >> 4, nq = (idx & 15)*4;
            int pn = nq ^ ((k & 3) << 3);
            const float* src = W + (size_t)(ksl*32 + k)*CDIM + bn + nq;
            uint32_t dst = sbRaw + (uint32_t)(buf*2048 + k*64 + pn)*4u;
            cp16(dst, src);
        }
        asm volatile("cp.async.commit_group;");
    };

    issue(0, 0);
    int buf = 0;
    for (int ksl = 0; ksl < 128; ksl++){
        asm volatile("cp.async.wait_group 0;");
        __syncthreads();
        if (ksl + 1 < 128) issue(ksl + 1, buf ^ 1);
        {
            const float* rb = sRaw + buf*2048;
            #pragma unroll
            for (int i = 0; i < 4; i++){
                int fi = i*256 + tid;
                int l = fi & 31, q = fi >> 5;
                int ct = q & 7, ks = q >> 3;
                int k1 = ks*8 + (l & 3);
                int n  = ct*8 + (l >> 2);
                float v1 = rb[k1*64 + (n ^ ((k1 & 3) << 3))];
                int k2 = k1 + 4;
                float v2 = rb[k2*64 + (n ^ ((k2 & 3) << 3))];
                float h1 = tf32r(v1), l1 = tf32r(v1 - h1);
                float h2 = tf32r(v2), l2 = tf32r(v2 - h2);
                sBF[(ks*8 + ct)*32 + l] = make_float4(h1, h2, l1, l2);
            }
        }
        __syncthreads();
        #pragma unroll
        for (int ks = 0; ks < 4; ks++){
            uint4 ah[2], al[2];
            #pragma unroll
            for (int mt = 0; mt < 2; mt++){
                int mtt = wmi*2 + mt;
                ah[mt] = *(const uint4*)&smem[buf*SA_F4 + ((0*4+ks)*4+mtt)*32 + lane];
                al[mt] = *(const uint4*)&smem[buf*SA_F4 + ((1*4+ks)*4+mtt)*32 + lane];
            }
            #pragma unroll
            for (int nt = 0; nt < NT; nt++){
                float4 bf = sBF[(ks*8 + wni*NT + nt)*32 + lane];
                unsigned bh[2] = {__float_as_uint(bf.x), __float_as_uint(bf.y)};
                unsigned bl[2] = {__float_as_uint(bf.z), __float_as_uint(bf.w)};
                #pragma unroll
                for (int mt = 0; mt < 2; mt++){
                    mma8(acc[mt][nt], (const unsigned*)&ah[mt], bl);
                    mma8(acc[mt][nt], (const unsigned*)&al[mt], bh);
                    mma8(acc[mt][nt], (const unsigned*)&ah[mt], bh);
                }
            }
        }
        buf ^= 1;
    }

    #pragma unroll
    for (int mt = 0; mt < 2; mt++){
        int row = (bm16 + wmi*2 + mt)*16 + gid;
        #pragma unroll
        for (int nt = 0; nt < NT; nt++){
            int col = bn + (wni*NT + nt)*8 + tig*2;
            float d0 = fmaxf(acc[mt][nt][0] + bias[col],   0.f);
            float d1 = fmaxf(acc[mt][nt][1] + bias[col+1], 0.f);
            float d2 = fmaxf(acc[mt][nt][2] + bias[col],   0.f);
            float d3 = fmaxf(acc[mt][nt][3] + bias[col+1], 0.f);
            *(float2*)(C + (size_t)row*CDIM + col)     = make_float2(d0, d1);
            *(float2*)(C + (size_t)(row+8)*CDIM + col) = make_float2(d2, d3);
        }
    }
}

// ---------------- build compressed-window MLP inputs (direct to A-frag) -------
__global__ void build_windows_kernel(const float* __restrict__ k_pos,
                                     const float* __restrict__ v_pos){
    int idx = blockIdx.x * 256 + threadIdx.x;
    int d = idx & 127;
    int j = (idx >> 7) & 31;
    int w = (idx >> 12) & 63;
    int h = (idx >> 18) & 1;
    int s = (idx >> 19) & 1;
    int t = w*16 + j - 16;
    const float* pos = s ? v_pos : k_pos;
    float pv = pos[(h*32 + j)*128 + d];
    float val = 0.f;
    if (t >= 0) val = g_qkv[(size_t)t*QKVW + (s ? 2304 : 2048) + h*128 + d];
    float v = val + pv;
    int row = h*64 + w;
    int k   = j*128 + d;
    float* ph = (float*)(g_AFh + (size_t)s*512*8*32);
    float* pl = (float*)(g_AFl + (size_t)s*512*8*32);
    afrag_store(ph, pl, 8, row, k, v);
}

// ---------------- fused gates + rope (after qkv) ----------
__global__ void gates_rope_kernel(const float* __restrict__ Wg){
    __shared__ float s_a[128][17];
    __shared__ float s_b[16][48];
    int id = blockIdx.x;
    int t = threadIdx.x;
    if (id < 128){
        int ks = id & 15, bm = (id >> 4) * 128;
        int rg = t >> 3, cg = t & 7;
        float acc[4][6];
        #pragma unroll
        for (int i = 0; i < 4; i++)
            #pragma unroll
            for (int j = 0; j < 6; j++) acc[i][j] = 0.f;
        int k0base = ks * 128;
        for (int kk = 0; kk < 128; kk += 16){
            int row = t >> 1, kh = (t & 1) * 8;
            const float* src = g_xn + (size_t)(bm + row)*XDIM + k0base + kk + kh;
            float4 v0 = *(const float4*)src, v1 = *(const float4*)(src + 4);
            s_a[row][kh+0]=v0.x; s_a[row][kh+1]=v0.y; s_a[row][kh+2]=v0.z; s_a[row][kh+3]=v0.w;
            s_a[row][kh+4]=v1.x; s_a[row][kh+5]=v1.y; s_a[row][kh+6]=v1.z; s_a[row][kh+7]=v1.w;
            #pragma unroll
            for (int i = 0; i < 3; i++){
                int idx = i*256 + t;
                s_b[idx/48][idx%48] = Wg[(size_t)(k0base + kk + idx/48)*48 + idx%48];
            }
            __syncthreads();
            #pragma unroll 4
            for (int k = 0; k < 16; k++){
                float a[4], b[6];
                #pragma unroll
                for (int i = 0; i < 4; i++) a[i] = s_a[rg*4 + i][k];
                #pragma unroll
                for (int j = 0; j < 6; j++) b[j] = s_b[k][cg*6 + j];
                #pragma unroll
                for (int i = 0; i < 4; i++)
                    #pragma unroll
                    for (int j = 0; j < 6; j++) acc[i][j] += a[i]*b[j];
            }
            __syncthreads();
        }
        #pragma unroll
        for (int i = 0; i < 4; i++)
            #pragma unroll
            for (int j = 0; j < 6; j++)
                g_gpart[(size_t)ks*NSEQ*48 + (size_t)(bm + rg*4 + i)*48 + cg*6 + j] = acc[i][j];
        return;
    }
    id -= 128;
    int p = id*4 + (t >> 6);
    int i = t & 63;
    int hh = p >> 10, n = p & 1023;
    float c = g_ropetab[(n*64 + i)*2 + 0];
    float s = g_ropetab[(n*64 + i)*2 + 1];
    const float* src; float* dst;
    if (hh < 16){
        src = g_qkv + (size_t)n*QKVW + hh*DH;
        dst = g_qrope + ((size_t)hh*NSEQ + n)*DH;
    } else {
        int h = hh - 16;
        src = g_qkv + (size_t)n*QKVW + 2048 + h*DH;
        dst = g_krope + ((size_t)h*NSEQ + n)*DH;
    }
    float x1 = src[2*i], x2 = src[2*i + 1];
    dst[2*i]     = x1*c - x2*s;
    dst[2*i + 1] = x1*s + x2*c;
}

// ---------------- MLP2: 128 blocks x 2 rows; writes ck/cv-full at j+1 --------
__global__ void mlp2_kernel(const float* __restrict__ Wk2, const float* __restrict__ bk2,
                            const float* __restrict__ Wv2, const float* __restrict__ bv2){
    int r0 = blockIdx.x * 2;
    int c  = threadIdx.x;
    const float* B    = (r0 < 128) ? Wk2 : Wv2;
    const float* bias = (r0 < 128) ? bk2 : bv2;
    __shared__ __align__(16) float s_a[2][1024];
    float acc[2] = {0.f, 0.f};
    for (int kc = 0; kc < 4096; kc += 1024){
        #pragma unroll
        for (int i = 0; i < 4; i++){
            int idx = i*128 + threadIdx.x;
            int rr = idx >> 8, cc = idx & 255;
            float4 v = *((const float4*)(g_hidden + (size_t)(r0 + rr)*4096 + kc) + cc);
            *((float4*)&s_a[rr][cc*4]) = v;
        }
        __syncthreads();
        #pragma unroll 4
        for (int k = 0; k < 1024; k++){
            float b = B[(size_t)(kc + k)*128 + c];
            acc[0] += s_a[0][k]*b; acc[1] += s_a[1][k]*b;
        }
        __syncthreads();
    }
    #pragma unroll
    for (int i = 0; i < 2; i++){
        int r = r0 + i;
        int s = r >> 7, rr = r & 127, h = rr >> 6, w = rr & 63;
        float* dst = s ? g_cvfull : g_ckfull;
        dst[(h*65 + 1 + w)*128 + c] = acc[i] + bias[c];
    }
}

// ---------------- compressed attention: thread-per-token QK (R11 form) -------
__global__ void cmp_attn_kernel(const float* __restrict__ mem_kv){
    int n = blockIdx.x, h = blockIdx.y;
    int tid = threadIdx.x, warp = tid >> 5, lane = tid & 31;
    __shared__ float s_l[8][65];
    __shared__ float s_imp[16];
    __shared__ __align__(16) float qs[8][128];

    {
        int gh = tid >> 5, c4 = (tid & 31)*4;
        *(float4*)&qs[gh][c4] =
            *(const float4*)(g_qkv + (size_t)n*QKVW + (h*GQH + gh)*DH + c4);
    }
    __syncthreads();

    if (tid < 65){
        const float4* kp = (tid == 0)
            ? (const float4*)(mem_kv + (size_t)h*DH)
            : (const float4*)(g_ckfull + (size_t)(h*65 + tid)*DH);
        float acc[8] = {0,0,0,0,0,0,0,0};
        #pragma unroll 8
        for (int dc = 0; dc < 32; dc++){
            float4 kv = kp[dc];
            #pragma unroll
            for (int gh = 0; gh < 8; gh++){
                float4 qv = *(const float4*)&qs[gh][dc*4];
                acc[gh] += qv.x*kv.x + qv.y*kv.y + qv.z*kv.z + qv.w*kv.w;
            }
        }
        #pragma unroll
        for (int gh = 0; gh < 8; gh++) s_l[gh][tid] = acc[gh] * SCALE;
    }
    __syncthreads();

    if (tid < 16){
        int f = tid;
        float s = 0.f;
        #pragma unroll
        for (int g = 0; g < 8; g++)
            #pragma unroll
            for (int w = 0; w < 4; w++) s += s_l[g][1 + f*4 + w];
        s *= (1.f / 32.f);
        if ((n >> 6) == f) s = NEGBIG;
        s_imp[f] = s;
    }
    __syncthreads();

    if (tid == 0){
        unsigned used = 0;
        int base = (h*NSEQ + n)*5;
        for (int r = 0; r < 4; r++){
            float best = -3.4e38f; int bi = 0;
            for (int f = 0; f < 16; f++)
                if (!((used >> f) & 1) && s_imp[f] > best){ best = s_imp[f]; bi = f; }
            used |= 1u << bi;
            g_sel[base + r] = bi;
        }
        g_sel[base + 4] = n >> 6;
    }

    float m = -3.4e38f;
    for (int j = lane; j < 65; j += 32) m = fmaxf(m, s_l[warp][j]);
    m = warp_max(m);
    float sum = 0.f;
    for (int j = lane; j < 65; j += 32){
        float e = __expf(s_l[warp][j] - m);
        s_l[warp][j] = e; sum += e;
    }
    sum = warp_sum(sum);
    float inv = 1.f / sum;

    float a0, a1, a2, a3;
    {
        float p = s_l[warp][0];
        float4 vv = *(const float4*)(mem_kv + (size_t)(KVH + h)*DH + lane*4);
        a0 = p*vv.x; a1 = p*vv.y; a2 = p*vv.z; a3 = p*vv.w;
    }
    #pragma unroll 4
    for (int j = 1; j < 65; j++){
        float p = s_l[warp][j];
        float4 vv = *(const float4*)(g_cvfull + (size_t)(h*65 + j)*DH + lane*4);
        a0 += p*vv.x; a1 += p*vv.y; a2 += p*vv.z; a3 += p*vv.w;
    }
    float* o = g_cmp + ((size_t)(h*GQH + warp)*NSEQ + n)*DH + lane*4;
    o[0] = a0*inv; o[1] = a1*inv; o[2] = a2*inv; o[3] = a3*inv;
}

// ---------------- fused fine + slide (R11 form, 320 threads, single QK wave) --
__global__ __launch_bounds__(320)
void fine_slide_kernel(){
    int n = blockIdx.x, h = blockIdx.y;
    int tid = threadIdx.x, warp = tid >> 5, lane = tid & 31;
    __shared__ __align__(16) float sT[8][320];     // [ghead][token]
    __shared__ __align__(16) float qs[8][128];
    __shared__ int s_blk[5];

    if (blockIdx.z == 0 && tid < 5) s_blk[tid] = g_sel[(h*NSEQ + n)*5 + tid];
    if (tid < 256){
        int gh = tid >> 5, c4 = (tid & 31)*4;
        *(float4*)&qs[gh][c4] =
            *(const float4*)(g_qrope + ((size_t)(h*GQH + gh)*NSEQ + n)*DH + c4);
    }
    __syncthreads();

    if (blockIdx.z == 0){
        // ---- fine: 320 tokens, one per thread (single wave) ----
        {
            int ti = tid;
            int tok = s_blk[ti >> 6]*64 + (ti & 63);
            const float4* kp = (const float4*)(g_krope + ((size_t)h*NSEQ + tok)*DH);
            float acc[8] = {0,0,0,0,0,0,0,0};
            #pragma unroll 8
            for (int dc = 0; dc < 32; dc++){
                float4 kv = kp[dc];
                #pragma unroll
                for (int gh = 0; gh < 8; gh++){
                    float4 qv = *(const float4*)&qs[gh][dc*4];
                    acc[gh] += qv.x*kv.x + qv.y*kv.y + qv.z*kv.z + qv.w*kv.w;
                }
            }
            #pragma unroll
            for (int gh = 0; gh < 8; gh++) sT[gh][ti] = acc[gh] * SCALE;
        }
        __syncthreads();

        if (warp < 8){
            float m = -3.4e38f;
            for (int t = lane; t < 320; t += 32) m = fmaxf(m, sT[warp][t]);
            m = warp_max(m);
            float sum = 0.f;
            for (int t = lane; t < 320; t += 32){
                float e = __expf(sT[warp][t] - m);
                sT[warp][t] = e; sum += e;
            }
            sum = warp_sum(sum);
            float inv = 1.f / sum;
            for (int t = lane; t < 320; t += 32) sT[warp][t] *= inv;
        }
        __syncthreads();

        if (tid < 256){
            int d = tid & 127, half = tid >> 7;
            int g0 = half*4;
            float a[4] = {0.f, 0.f, 0.f, 0.f};
            #pragma unroll
            for (int b = 0; b < 5; b++){
                size_t vbase = (size_t)s_blk[b]*64*QKVW + 2304 + h*DH + d;
                #pragma unroll 4
                for (int tt = 0; tt < 64; tt += 4){
                    float v0 = g_qkv[vbase + (size_t)(tt+0)*QKVW];
                    float v1 = g_qkv[vbase + (size_t)(tt+1)*QKVW];
                    float v2 = g_qkv[vbase + (size_t)(tt+2)*QKVW];
                    float v3 = g_qkv[vbase + (size_t)(tt+3)*QKVW];
                    int t0 = b*64 + tt;
                    #pragma unroll
                    for (int gg = 0; gg < 4; gg++){
                        a[gg] += sT[g0+gg][t0+0]*v0 + sT[g0+gg][t0+1]*v1
                               + sT[g0+gg][t0+2]*v2 + sT[g0+gg][t0+3]*v3;
                    }
                }
            }
            #pragma unroll
            for (int gg = 0; gg < 4; gg++)
                g_fine[((size_t)(h*GQH + g0 + gg)*NSEQ + n)*DH + d] = a[gg];
        }
    } else {
        // ---- slide: up to 257 tokens, one per thread (single wave) ----
        int lo = n - 128; if (lo < 0) lo = 0;
        int hi = n + 128; if (hi > NSEQ - 1) hi = NSEQ - 1;
        int cnt = hi - lo + 1;

        if (tid < cnt){
            int ti = tid;
            const float4* kp = (const float4*)(g_krope + ((size_t)h*NSEQ + lo + ti)*DH);
            float acc[8] = {0,0,0,0,0,0,0,0};
            #pragma unroll 8
            for (int dc = 0; dc < 32; dc++){
                float4 kv = kp[dc];
                #pragma unroll
                for (int gh = 0; gh < 8; gh++){
                    float4 qv = *(const float4*)&qs[gh][dc*4];
                    acc[gh] += qv.x*kv.x + qv.y*kv.y + qv.z*kv.z + qv.w*kv.w;
                }
            }
            #pragma unroll
            for (int gh = 0; gh < 8; gh++) sT[gh][ti] = acc[gh] * SCALE;
        }
        __syncthreads();

        if (warp < 8){
            float m = -3.4e38f;
            for (int t = lane; t < cnt; t += 32) m = fmaxf(m, sT[warp][t]);
            m = warp_max(m);
            float sum = 0.f;
            for (int t = lane; t < cnt; t += 32){
                float e = __expf(sT[warp][t] - m);
                sT[warp][t] = e; sum += e;
            }
            sum = warp_sum(sum);
            float inv = 1.f / sum;
            for (int t = lane; t < cnt; t += 32) sT[warp][t] *= inv;
        }
        __syncthreads();

        if (tid < 256){
            int d = tid & 127, half = tid >> 7;
            int g0 = half*4;
            float a[4] = {0.f, 0.f, 0.f, 0.f};
            size_t vbase = (size_t)lo*QKVW + 2304 + h*DH + d;
            int cnt4 = cnt & ~3;
            #pragma unroll 4
            for (int tt = 0; tt < cnt4; tt += 4){
                float v0 = g_qkv[vbase + (size_t)(tt+0)*QKVW];
                float v1 = g_qkv[vbase + (size_t)(tt+1)*QKVW];
                float v2 = g_qkv[vbase + (size_t)(tt+2)*QKVW];
                float v3 = g_qkv[vbase + (size_t)(tt+3)*QKVW];
                #pragma unroll
                for (int gg = 0; gg < 4; gg++){
                    a[gg] += sT[g0+gg][tt+0]*v0 + sT[g0+gg][tt+1]*v1
                           + sT[g0+gg][tt+2]*v2 + sT[g0+gg][tt+3]*v3;
                }
            }
            for (int tt = cnt4; tt < cnt; tt++){
                float v = g_qkv[vbase + (size_t)tt*QKVW];
                #pragma unroll
                for (int gg = 0; gg < 4; gg++) a[gg] += sT[g0+gg][tt]*v;
            }
            #pragma unroll
            for (int gg = 0; gg < 4; gg++)
                g_slide[((size_t)(h*GQH + g0 + gg)*NSEQ + n)*DH + d] = a[gg];
        }
    }
}

// ---------------- gate-weighted combine -> O1 A-frag (hi only) ----------------
__global__ void combine_kernel(const float* __restrict__ bg){
    int n = blockIdx.x, hq = blockIdx.y, d = threadIdx.x;
    __shared__ float sg[3];
    if (d < 3){
        float s = bg[hq*3 + d];
        #pragma unroll
        for (int p = 0; p < 16; p++)
            s += g_gpart[(size_t)p*NSEQ*48 + (size_t)n*48 + hq*3 + d];
        sg[d] = 1.f / (1.f + __expf(-s));
    }
    __syncthreads();
    float g0 = sg[0], g1 = sg[1], g2 = sg[2];
    size_t idx = ((size_t)hq*NSEQ + n)*DH + d;
    float o = g_cmp[idx]*g0 + g_fine[idx]*g1 + g_slide[idx]*g2;
    int k = hq*128 + d;
    int ks = k >> 3, mt = n >> 4;
    int lane = (n & 7)*4 + (k & 3);
    int slot = ((n >> 3) & 1) + 2*((k >> 2) & 1);
    ((float*)g_AOh)[(((size_t)ks*64 + mt)*32 + lane)*4 + slot] = tf32r(o);
}

// ---------------- launch ----------------
extern "C" void kernel_launch(void* const* d_in, const int* in_sizes, int n_in,
                              void* d_out, int out_size){
    const float* x      = (const float*)d_in[0];
    const float* g_norm = (const float*)d_in[1];
    const float* W_qkv  = (const float*)d_in[2];
    const float* k_pos  = (const float*)d_in[3];
    const float* v_pos  = (const float*)d_in[4];
    const float* mem_kv = (const float*)d_in[5];
    const float* Wk1    = (const float*)d_in[6];
    const float* bk1    = (const float*)d_in[7];
    const float* Wk2    = (const float*)d_in[8];
    const float* bk2    = (const float*)d_in[9];
    const float* Wv1    = (const float*)d_in[10];
    const float* bv1    = (const float*)d_in[11];
    const float* Wv2    = (const float*)d_in[12];
    const float* bv2    = (const float*)d_in[13];
    const float* Wg     = (const float*)d_in[14];
    const float* bg     = (const float*)d_in[15];
    const float* W_out  = (const float*)d_in[16];
    float* out = (float*)d_out;

    cudaFuncSetAttribute(gemm_tc<true>,  cudaFuncAttributeMaxDynamicSharedMemorySize, 98304);
    cudaFuncSetAttribute(gemm_tc<false>, cudaFuncAttributeMaxDynamicSharedMemorySize, 49152);
    cudaFuncSetAttribute(gemm_mlp1,      cudaFuncAttributeMaxDynamicSharedMemorySize, 65536);

    float4 *p_BFq, *p_AXh, *p_AXl, *p_AOh;
    float2 *p_BFo;
    float *p_qkv;
    cudaGetSymbolAddress((void**)&p_BFq,  g_BFq);
    cudaGetSymbolAddress((void**)&p_BFo,  g_BFo);
    cudaGetSymbolAddress((void**)&p_AXh,  g_AXh);
    cudaGetSymbolAddress((void**)&p_AXl,  g_AXl);
    cudaGetSymbolAddress((void**)&p_AOh,  g_AOh);
    cudaGetSymbolAddress((void**)&p_qkv,  g_qkv);

    // 0: rmsnorm + weight preps + rope table
    stage0_kernel<<<3584, 256>>>(x, g_norm, W_qkv, W_out);
    // 1: qkv = xn @ W_qkv (3xTF32)
    gemm_tc<true><<<dim3(QKVW/64, NSEQ/128), 256, 98304>>>(
        p_AXh, p_AXl, p_BFq, nullptr, p_qkv, 64, QKVW, XDIM, 0);
    // 2: build MLP inputs
    build_windows_kernel<<<4096, 256>>>(k_pos, v_pos);
    // 3 (ncu-captured): MLP1 k & v
    gemm_mlp1<<<dim3(CDIM/64, 2, 2), 256, 65536>>>(Wk1, Wv1, bk1, bv1);
    // 4: gates + rope
    gates_rope_kernel<<<4736, 256>>>(Wg);
    // 5: MLP2 -> ck/cv-full
    mlp2_kernel<<<128, 128>>>(Wk2, bk2, Wv2, bv2);
    // 6: compressed attention + selection (R11 form)
    cmp_attn_kernel<<<dim3(NSEQ, KVH), 256>>>(mem_kv);
    // 7: fine + slide (R11 form, 320 threads, single QK wave)
    fine_slide_kernel<<<dim3(NSEQ, KVH, 2), 320>>>();
    // 8: combine
    combine_kernel<<<dim3(NSEQ, NHEADS), 128>>>(bg);
    // 9: out = O1 @ W_out (plain TF32)
    gemm_tc<false><<<dim3(XDIM/64, NSEQ/128), 256, 49152>>>(
        p_AOh, nullptr, p_BFo, nullptr, out, 64, XDIM, XDIM, 0);
}

// round 16
// speedup vs baseline: 1.0662x; 1.0662x over previous
#include <cuda_runtime.h>
#include <math.h>
#include <stdint.h>

#define NSEQ   1024
#define XDIM   2048
#define NHEADS 16
#define KVH    2
#define GQH    8
#define DH     128
#define QKVW   2560      // 2048 + 256 + 256
#define CDIM   4096      // CMP_BLK * DH
#define SCALE  0.08838834764831845f
#define NEGBIG -1e10f

// ---------------- scratch (device globals; no runtime allocation) ----------------
__device__ __align__(128) float g_xn    [NSEQ*XDIM];
__device__ __align__(128) float g_qkv   [NSEQ*QKVW];
__device__ __align__(128) float g_hidden[2*128*CDIM];
__device__ __align__(128) float g_ckfull[KVH*65*DH];
__device__ __align__(128) float g_cvfull[KVH*65*DH];
__device__ __align__(128) float g_cmp   [NHEADS*NSEQ*DH];
__device__ __align__(128) float g_fine  [NHEADS*NSEQ*DH];
__device__ __align__(128) float g_slide [NHEADS*NSEQ*DH];
__device__ __align__(128) float g_qrope [NHEADS*NSEQ*DH];
__device__ __align__(128) float g_krope [KVH*NSEQ*DH];
__device__ __align__(128) float g_ropetab[NSEQ*64*2];
__device__ __align__(128) float g_gpart [16*NSEQ*48];
__device__ int g_sel[KVH*NSEQ*5];

// fragment-layout operand buffers
__device__ float4 g_BFq [256*320*32];       // W_qkv (split)
__device__ float2 g_BFo [256*256*32];       // W_out (plain)
__device__ float4 g_AXh[256*64*32],  g_AXl[256*64*32];    // xn
__device__ float4 g_AFh[2*512*8*32], g_AFl[2*512*8*32];   // compress-MLP inputs
__device__ float4 g_AOh[256*64*32];                       // combined O1 (hi only)

// ---------------- helpers ----------------
__device__ __forceinline__ float warp_sum(float v){
    #pragma unroll
    for (int o = 16; o > 0; o >>= 1) v += __shfl_xor_sync(0xffffffffu, v, o);
    return v;
}
__device__ __forceinline__ float warp_max(float v){
    #pragma unroll
    for (int o = 16; o > 0; o >>= 1) v = fmaxf(v, __shfl_xor_sync(0xffffffffu, v, o));
    return v;
}
__device__ __forceinline__ float tf32r(float x){
    unsigned r; asm("cvt.rna.tf32.f32 %0, %1;" : "=r"(r) : "f"(x));
    return __uint_as_float(r);
}
__device__ __forceinline__ void mma8(float* d, const unsigned* a, const unsigned* b){
    asm volatile("mma.sync.aligned.m16n8k8.row.col.f32.tf32.tf32.f32 "
        "{%0,%1,%2,%3},{%4,%5,%6,%7},{%8,%9},{%0,%1,%2,%3};"
        : "+f"(d[0]),"+f"(d[1]),"+f"(d[2]),"+f"(d[3])
        : "r"(a[0]),"r"(a[1]),"r"(a[2]),"r"(a[3]),"r"(b[0]),"r"(b[1]));
}
__device__ __forceinline__ void cp16(uint32_t s, const void* g){
    asm volatile("cp.async.cg.shared.global [%0], [%1], 16;" :: "r"(s), "l"(g));
}
__device__ __forceinline__ void cp8(uint32_t s, const void* g){
    asm volatile("cp.async.ca.shared.global [%0], [%1], 8;" :: "r"(s), "l"(g));
}
__device__ __forceinline__ void afrag_store(float* ph, float* pl, int M16,
                                            int row, int k, float v){
    int ks = k >> 3, mt = row >> 4;
    int lane = (row & 7)*4 + (k & 3);
    int slot = ((row >> 3) & 1) + 2*((k >> 2) & 1);
    size_t fi = (((size_t)ks*M16 + mt)*32 + lane)*4 + slot;
    float h = tf32r(v);
    ph[fi] = h;
    pl[fi] = tf32r(v - h);
}

// ---------------- weight prep bodies ----------------
__device__ __forceinline__ void prep4_body(const float* __restrict__ W,
                                           float4* __restrict__ BF, int N,
                                           int bx, int by, float (*sw)[65]){
    int n0 = bx*64, k0 = by*64;
    int t = threadIdx.x;
    #pragma unroll
    for (int ii = 0; ii < 4; ii++){
        int r = ii*16 + (t >> 4), c4 = (t & 15)*4;
        float4 v = *(const float4*)(W + (size_t)(k0 + r)*N + n0 + c4);
        sw[r][c4+0]=v.x; sw[r][c4+1]=v.y; sw[r][c4+2]=v.z; sw[r][c4+3]=v.w;
    }
    __syncthreads();
    int lane = t & 31, ct = t >> 5;
    int c = lane & 3, gcol = lane >> 2;
    #pragma unroll
    for (int i = 0; i < 8; i++){
        float v1 = sw[i*8 + c][ct*8 + gcol];
        float v2 = sw[i*8 + 4 + c][ct*8 + gcol];
        float h1 = tf32r(v1), l1 = tf32r(v1 - h1);
        float h2 = tf32r(v2), l2 = tf32r(v2 - h2);
        BF[((size_t)(k0/8 + i)*(N >> 3) + (n0 >> 3) + ct)*32 + lane] =
            make_float4(h1, h2, l1, l2);
    }
}
__device__ __forceinline__ void prep2_body(const float* __restrict__ W,
                                           float2* __restrict__ BF, int N,
                                           int bx, int by, float (*sw)[65]){
    int n0 = bx*64, k0 = by*64;
    int t = threadIdx.x;
    #pragma unroll
    for (int ii = 0; ii < 4; ii++){
        int r = ii*16 + (t >> 4), c4 = (t & 15)*4;
        float4 v = *(const float4*)(W + (size_t)(k0 + r)*N + n0 + c4);
        sw[r][c4+0]=v.x; sw[r][c4+1]=v.y; sw[r][c4+2]=v.z; sw[r][c4+3]=v.w;
    }
    __syncthreads();
    int lane = t & 31, ct = t >> 5;
    int c = lane & 3, gcol = lane >> 2;
    #pragma unroll
    for (int i = 0; i < 8; i++){
        float v1 = sw[i*8 + c][ct*8 + gcol];
        float v2 = sw[i*8 + 4 + c][ct*8 + gcol];
        BF[((size_t)(k0/8 + i)*(N >> 3) + (n0 >> 3) + ct)*32 + lane] =
            make_float2(tf32r(v1), tf32r(v2));
    }
}

// ---------------- fused stage0: rmsnorm + weight preps + rope table ----------
__global__ void stage0_kernel(const float* __restrict__ x, const float* __restrict__ g,
                              const float* __restrict__ Wq, const float* __restrict__ Wo){
    __shared__ float sw[64][65];
    int id = blockIdx.x;
    int tid = threadIdx.x;
    if (id < 1024){
        int n = id;
        const float4* row = (const float4*)(x + (size_t)n*XDIM);
        float s = 0.f;
        for (int i = tid; i < XDIM/4; i += 256){
            float4 v = row[i];
            s += v.x*v.x + v.y*v.y + v.z*v.z + v.w*v.w;
        }
        s = warp_sum(s);
        __shared__ float red[8];
        __shared__ float tot;
        if ((tid & 31) == 0) red[tid >> 5] = s;
        __syncthreads();
        if (tid < 32){
            float v = (tid < 8) ? red[tid] : 0.f;
            v = warp_sum(v);
            if (tid == 0) tot = rsqrtf(v / (float)XDIM + 1e-6f);
        }
        __syncthreads();
        float inv = tot;
        const float4* gg = (const float4*)g;
        float4* op = (float4*)(g_xn + (size_t)n*XDIM);
        float* ph = (float*)g_AXh;
        float* pl = (float*)g_AXl;
        for (int i = tid; i < XDIM/4; i += 256){
            float4 v = row[i], w = gg[i], o;
            o.x = v.x*inv*w.x; o.y = v.y*inv*w.y; o.z = v.z*inv*w.z; o.w = v.w*inv*w.w;
            op[i] = o;
            int k0 = i*4;
            afrag_store(ph, pl, 64, n, k0+0, o.x);
            afrag_store(ph, pl, 64, n, k0+1, o.y);
            afrag_store(ph, pl, 64, n, k0+2, o.z);
            afrag_store(ph, pl, 64, n, k0+3, o.w);
        }
        return;
    }
    id -= 1024;
    if (id < 1280){ prep4_body(Wq, g_BFq, QKVW, id % 40, id / 40, sw); return; }
    id -= 1280;
    if (id < 1024){ prep2_body(Wo, g_BFo, XDIM, id % 32, id / 32, sw); return; }
    id -= 1024;
    int idx = id * 256 + tid;
    int i = idx & 63, n = idx >> 6;
    double f = exp(-((double)(2*i) / 128.0) * 9.210340371976184);
    double ang = (double)n * f;
    g_ropetab[idx*2 + 0] = (float)cos(ang);
    g_ropetab[idx*2 + 1] = (float)sin(ang);
}

// ---------------- tensor-core GEMM (prepped B frags in gmem) ----------------
template<bool SPLIT>
__global__ __launch_bounds__(256)
void gemm_tc(const float4* __restrict__ AFh, const float4* __restrict__ AFl,
             const void* __restrict__ BFv,
             const float* __restrict__ bias,
             float* __restrict__ C,
             int M16, int N, int K, int relu){
    constexpr int MT16 = 8;
    constexpr int NT = 4;
    constexpr int APS = SPLIT ? 2 : 1;
    constexpr int SA_F4 = APS*4*MT16*32;
    constexpr int SB_EL = 4*8*32;

    extern __shared__ float4 smem[];
    char* sBraw = (char*)(smem + 2*SA_F4);

    int tid = threadIdx.x, lane = tid & 31, warp = tid >> 5;
    int bm16 = blockIdx.y*MT16;
    int bn8  = blockIdx.x*8;
    int wmi = warp & 3, wni = warp >> 2;
    int gid = lane >> 2, tig = lane & 3;
    int N8 = N >> 3;

    uint32_t sbase = (uint32_t)__cvta_generic_to_shared(smem);
    uint32_t sbB   = (uint32_t)__cvta_generic_to_shared(sBraw);

    float acc[2][NT][4];
    #pragma unroll
    for (int i = 0; i < 2; i++)
        #pragma unroll
        for (int j = 0; j < NT; j++)
            #pragma unroll
            for (int e = 0; e < 4; e++) acc[i][j][e] = 0.f;

    auto issue = [&](int ksl, int buf){
        #pragma unroll
        for (int i = 0; i < APS*4*MT16*32/256; i++){
            int idx = i*256 + tid;
            int l = idx & 31, q = idx >> 5;
            int mt = q % MT16, ks = (q/MT16) & 3, a = q/(MT16*4);
            const float4* src = (SPLIT && a ? AFl : AFh)
                + ((size_t)(ksl*4 + ks)*M16 + bm16 + mt)*32 + l;
            uint32_t dst = sbase + (uint32_t)(buf*SA_F4 + ((a*4+ks)*MT16+mt)*32+l)*16u;
            cp16(dst, src);
        }
        #pragma unroll
        for (int i = 0; i < 4; i++){
            int idx = i*256 + tid;
            int l = idx & 31, ct = (idx >> 5) & 7, ks = idx >> 8;
            size_t si = ((size_t)(ksl*4 + ks)*N8 + bn8 + ct)*32 + l;
            uint32_t dst = sbB + (uint32_t)(buf*SB_EL + (ks*8+ct)*32 + l)*(SPLIT?16u:8u);
            if (SPLIT) cp16(dst, (const float4*)BFv + si);
            else       cp8 (dst, (const float2*)BFv + si);
        }
        asm volatile("cp.async.commit_group;");
    };

    int nslab = K/32;
    issue(0, 0);
    int buf = 0;
    for (int ksl = 0; ksl < nslab; ksl++){
        asm volatile("cp.async.wait_group 0;");
        __syncthreads();
        if (ksl + 1 < nslab) issue(ksl + 1, buf ^ 1);
        #pragma unroll
        for (int ks = 0; ks < 4; ks++){
            uint4 ah[2], al[2];
            #pragma unroll
            for (int mt = 0; mt < 2; mt++){
                int mtt = wmi*2 + mt;
                ah[mt] = *(const uint4*)&smem[buf*SA_F4 + ((0*4+ks)*MT16+mtt)*32 + lane];
                if (SPLIT)
                    al[mt] = *(const uint4*)&smem[buf*SA_F4 + ((1*4+ks)*MT16+mtt)*32 + lane];
            }
            #pragma unroll
            for (int nt = 0; nt < NT; nt++){
                int bi = (ks*8 + wni*NT + nt)*32 + lane;
                unsigned bh[2], bl[2];
                if (SPLIT){
                    float4 bf = ((const float4*)sBraw)[buf*SB_EL + bi];
                    bh[0]=__float_as_uint(bf.x); bh[1]=__float_as_uint(bf.y);
                    bl[0]=__float_as_uint(bf.z); bl[1]=__float_as_uint(bf.w);
                } else {
                    float2 bf = ((const float2*)sBraw)[buf*SB_EL + bi];
                    bh[0]=__float_as_uint(bf.x); bh[1]=__float_as_uint(bf.y);
                }
                #pragma unroll
                for (int mt = 0; mt < 2; mt++){
                    if (SPLIT){
                        mma8(acc[mt][nt], (const unsigned*)&ah[mt], bl);
                        mma8(acc[mt][nt], (const unsigned*)&al[mt], bh);
                    }
                    mma8(acc[mt][nt], (const unsigned*)&ah[mt], bh);
                }
            }
        }
        buf ^= 1;
    }

    #pragma unroll
    for (int mt = 0; mt < 2; mt++){
        int row = (bm16 + wmi*2 + mt)*16 + gid;
        #pragma unroll
        for (int nt = 0; nt < NT; nt++){
            int col = (bn8 + wni*NT + nt)*8 + tig*2;
            float b0 = bias ? bias[col]   : 0.f;
            float b1 = bias ? bias[col+1] : 0.f;
            float d0 = acc[mt][nt][0] + b0, d1 = acc[mt][nt][1] + b1;
            float d2 = acc[mt][nt][2] + b0, d3 = acc[mt][nt][3] + b1;
            if (relu){
                d0 = fmaxf(d0, 0.f); d1 = fmaxf(d1, 0.f);
                d2 = fmaxf(d2, 0.f); d3 = fmaxf(d3, 0.f);
            }
            *(float2*)(C + (size_t)row*N + col)     = make_float2(d0, d1);
            *(float2*)(C + (size_t)(row+8)*N + col) = make_float2(d2, d3);
        }
    }
}

// ---------------- MLP1 GEMM: BM=64, raw B weights, in-kernel split conversion --
__global__ __launch_bounds__(256)
void gemm_mlp1(const float* __restrict__ Wk1, const float* __restrict__ Wv1,
               const float* __restrict__ bk1, const float* __restrict__ bv1){
    constexpr int NT = 2;
    constexpr int SA_F4 = 2*4*4*32;
    extern __shared__ float4 smem[];
    float* sRaw  = (float*)(smem + 2*SA_F4);
    float4* sBF  = (float4*)(sRaw + 2*32*64);

    const float* W    = blockIdx.z ? Wv1 : Wk1;
    const float* bias = blockIdx.z ? bv1 : bk1;
    const float4* AFh = g_AFh + (size_t)blockIdx.z*512*8*32;
    const float4* AFl = g_AFl + (size_t)blockIdx.z*512*8*32;
    float* C = g_hidden + (size_t)blockIdx.z*128*CDIM;

    int tid = threadIdx.x, lane = tid & 31, warp = tid >> 5;
    int bn = blockIdx.x*64;
    int bm16 = blockIdx.y*4;
    int wmi = warp & 1, wni = warp >> 1;
    int gid = lane >> 2, tig = lane & 3;

    uint32_t sbase = (uint32_t)__cvta_generic_to_shared(smem);
    uint32_t sbRaw = (uint32_t)__cvta_generic_to_shared(sRaw);

    float acc[2][NT][4];
    #pragma unroll
    for (int i = 0; i < 2; i++)
        #pragma unroll
        for (int j = 0; j < NT; j++)
            #pragma unroll
            for (int e = 0; e < 4; e++) acc[i][j][e] = 0.f;

    auto issue = [&](int ksl, int buf){
        #pragma unroll
        for (int i = 0; i < 4; i++){
            int idx = i*256 + tid;
            int l = idx & 31, q = idx >> 5;
            int mt = q & 3, ks = (q >> 2) & 3, a = q >> 4;
            const float4* src = (a ? AFl : AFh)
                + ((size_t)(ksl*4 + ks)*8 + bm16 + mt)*32 + l;
            uint32_t dst = sbase + (uint32_t)(buf*SA_F4 + ((a*4+ks)*4+mt)*32+l)*16u;
            cp16(dst, src);
        }
        #pragma unroll
        for (int i = 0; i < 2; i++){
            int idx = i*256 + tid;
            int k = idx >> 4, nq = (idx & 15)*4;
            int pn = nq ^ ((k & 3) << 3);
            const float* src = W + (size_t)(ksl*32 + k)*CDIM + bn + nq;
            uint32_t dst = sbRaw + (uint32_t)(buf*2048 + k*64 + pn)*4u;
            cp16(dst, src);
        }
        asm volatile("cp.async.commit_group;");
    };

    issue(0, 0);
    int buf = 0;
    for (int ksl = 0; ksl < 128; ksl++){
        asm volatile("cp.async.wait_group 0;");
        __syncthreads();
        if (ksl + 1 < 128) issue(ksl + 1, buf ^ 1);
        {
            const float* rb = sRaw + buf*2048;
            #pragma unroll
            for (int i = 0; i < 4; i++){
                int fi = i*256 + tid;
                int l = fi & 31, q = fi >> 5;
                int ct = q & 7, ks = q >> 3;
                int k1 = ks*8 + (l & 3);
                int n  = ct*8 + (l >> 2);
                float v1 = rb[k1*64 + (n ^ ((k1 & 3) << 3))];
                int k2 = k1 + 4;
                float v2 = rb[k2*64 + (n ^ ((k2 & 3) << 3))];
                float h1 = tf32r(v1), l1 = tf32r(v1 - h1);
                float h2 = tf32r(v2), l2 = tf32r(v2 - h2);
                sBF[(ks*8 + ct)*32 + l] = make_float4(h1, h2, l1, l2);
            }
        }
        __syncthreads();
        #pragma unroll
        for (int ks = 0; ks < 4; ks++){
            uint4 ah[2], al[2];
            #pragma unroll
            for (int mt = 0; mt < 2; mt++){
                int mtt = wmi*2 + mt;
                ah[mt] = *(const uint4*)&smem[buf*SA_F4 + ((0*4+ks)*4+mtt)*32 + lane];
                al[mt] = *(const uint4*)&smem[buf*SA_F4 + ((1*4+ks)*4+mtt)*32 + lane];
            }
            #pragma unroll
            for (int nt = 0; nt < NT; nt++){
                float4 bf = sBF[(ks*8 + wni*NT + nt)*32 + lane];
                unsigned bh[2] = {__float_as_uint(bf.x), __float_as_uint(bf.y)};
                unsigned bl[2] = {__float_as_uint(bf.z), __float_as_uint(bf.w)};
                #pragma unroll
                for (int mt = 0; mt < 2; mt++){
                    mma8(acc[mt][nt], (const unsigned*)&ah[mt], bl);
                    mma8(acc[mt][nt], (const unsigned*)&al[mt], bh);
                    mma8(acc[mt][nt], (const unsigned*)&ah[mt], bh);
                }
            }
        }
        buf ^= 1;
    }

    #pragma unroll
    for (int mt = 0; mt < 2; mt++){
        int row = (bm16 + wmi*2 + mt)*16 + gid;
        #pragma unroll
        for (int nt = 0; nt < NT; nt++){
            int col = bn + (wni*NT + nt)*8 + tig*2;
            float d0 = fmaxf(acc[mt][nt][0] + bias[col],   0.f);
            float d1 = fmaxf(acc[mt][nt][1] + bias[col+1], 0.f);
            float d2 = fmaxf(acc[mt][nt][2] + bias[col],   0.f);
            float d3 = fmaxf(acc[mt][nt][3] + bias[col+1], 0.f);
            *(float2*)(C + (size_t)row*CDIM + col)     = make_float2(d0, d1);
            *(float2*)(C + (size_t)(row+8)*CDIM + col) = make_float2(d2, d3);
        }
    }
}

// ---------------- build compressed-window MLP inputs (direct to A-frag) -------
__global__ void build_windows_kernel(const float* __restrict__ k_pos,
                                     const float* __restrict__ v_pos){
    int idx = blockIdx.x * 256 + threadIdx.x;
    int d = idx & 127;
    int j = (idx >> 7) & 31;
    int w = (idx >> 12) & 63;
    int h = (idx >> 18) & 1;
    int s = (idx >> 19) & 1;
    int t = w*16 + j - 16;
    const float* pos = s ? v_pos : k_pos;
    float pv = pos[(h*32 + j)*128 + d];
    float val = 0.f;
    if (t >= 0) val = g_qkv[(size_t)t*QKVW + (s ? 2304 : 2048) + h*128 + d];
    float v = val + pv;
    int row = h*64 + w;
    int k   = j*128 + d;
    float* ph = (float*)(g_AFh + (size_t)s*512*8*32);
    float* pl = (float*)(g_AFl + (size_t)s*512*8*32);
    afrag_store(ph, pl, 8, row, k, v);
}

// ---------------- fused gates + rope (after qkv) ----------
__global__ void gates_rope_kernel(const float* __restrict__ Wg){
    __shared__ float s_a[128][17];
    __shared__ float s_b[16][48];
    int id = blockIdx.x;
    int t = threadIdx.x;
    if (id < 128){
        int ks = id & 15, bm = (id >> 4) * 128;
        int rg = t >> 3, cg = t & 7;
        float acc[4][6];
        #pragma unroll
        for (int i = 0; i < 4; i++)
            #pragma unroll
            for (int j = 0; j < 6; j++) acc[i][j] = 0.f;
        int k0base = ks * 128;
        for (int kk = 0; kk < 128; kk += 16){
            int row = t >> 1, kh = (t & 1) * 8;
            const float* src = g_xn + (size_t)(bm + row)*XDIM + k0base + kk + kh;
            float4 v0 = *(const float4*)src, v1 = *(const float4*)(src + 4);
            s_a[row][kh+0]=v0.x; s_a[row][kh+1]=v0.y; s_a[row][kh+2]=v0.z; s_a[row][kh+3]=v0.w;
            s_a[row][kh+4]=v1.x; s_a[row][kh+5]=v1.y; s_a[row][kh+6]=v1.z; s_a[row][kh+7]=v1.w;
            #pragma unroll
            for (int i = 0; i < 3; i++){
                int idx = i*256 + t;
                s_b[idx/48][idx%48] = Wg[(size_t)(k0base + kk + idx/48)*48 + idx%48];
            }
            __syncthreads();
            #pragma unroll 4
            for (int k = 0; k < 16; k++){
                float a[4], b[6];
                #pragma unroll
                for (int i = 0; i < 4; i++) a[i] = s_a[rg*4 + i][k];
                #pragma unroll
                for (int j = 0; j < 6; j++) b[j] = s_b[k][cg*6 + j];
                #pragma unroll
                for (int i = 0; i < 4; i++)
                    #pragma unroll
                    for (int j = 0; j < 6; j++) acc[i][j] += a[i]*b[j];
            }
            __syncthreads();
        }
        #pragma unroll
        for (int i = 0; i < 4; i++)
            #pragma unroll
            for (int j = 0; j < 6; j++)
                g_gpart[(size_t)ks*NSEQ*48 + (size_t)(bm + rg*4 + i)*48 + cg*6 + j] = acc[i][j];
        return;
    }
    id -= 128;
    int p = id*4 + (t >> 6);
    int i = t & 63;
    int hh = p >> 10, n = p & 1023;
    float c = g_ropetab[(n*64 + i)*2 + 0];
    float s = g_ropetab[(n*64 + i)*2 + 1];
    const float* src; float* dst;
    if (hh < 16){
        src = g_qkv + (size_t)n*QKVW + hh*DH;
        dst = g_qrope + ((size_t)hh*NSEQ + n)*DH;
    } else {
        int h = hh - 16;
        src = g_qkv + (size_t)n*QKVW + 2048 + h*DH;
        dst = g_krope + ((size_t)h*NSEQ + n)*DH;
    }
    float x1 = src[2*i], x2 = src[2*i + 1];
    dst[2*i]     = x1*c - x2*s;
    dst[2*i + 1] = x1*s + x2*c;
}

// ---------------- MLP2: 128 blocks x 2 rows; writes ck/cv-full at j+1 --------
__global__ void mlp2_kernel(const float* __restrict__ Wk2, const float* __restrict__ bk2,
                            const float* __restrict__ Wv2, const float* __restrict__ bv2){
    int r0 = blockIdx.x * 2;
    int c  = threadIdx.x;
    const float* B    = (r0 < 128) ? Wk2 : Wv2;
    const float* bias = (r0 < 128) ? bk2 : bv2;
    __shared__ __align__(16) float s_a[2][1024];
    float acc[2] = {0.f, 0.f};
    for (int kc = 0; kc < 4096; kc += 1024){
        #pragma unroll
        for (int i = 0; i < 4; i++){
            int idx = i*128 + threadIdx.x;
            int rr = idx >> 8, cc = idx & 255;
            float4 v = *((const float4*)(g_hidden + (size_t)(r0 + rr)*4096 + kc) + cc);
            *((float4*)&s_a[rr][cc*4]) = v;
        }
        __syncthreads();
        #pragma unroll 4
        for (int k = 0; k < 1024; k++){
            float b = B[(size_t)(kc + k)*128 + c];
            acc[0] += s_a[0][k]*b; acc[1] += s_a[1][k]*b;
        }
        __syncthreads();
    }
    #pragma unroll
    for (int i = 0; i < 2; i++){
        int r = r0 + i;
        int s = r >> 7, rr = r & 127, h = rr >> 6, w = rr & 63;
        float* dst = s ? g_cvfull : g_ckfull;
        dst[(h*65 + 1 + w)*128 + c] = acc[i] + bias[c];
    }
}

// ---------------- compressed attention: thread-per-token QK (R11 form) -------
__global__ void cmp_attn_kernel(const float* __restrict__ mem_kv){
    int n = blockIdx.x, h = blockIdx.y;
    int tid = threadIdx.x, warp = tid >> 5, lane = tid & 31;
    __shared__ float s_l[8][65];
    __shared__ float s_imp[16];
    __shared__ __align__(16) float qs[8][128];

    {
        int gh = tid >> 5, c4 = (tid & 31)*4;
        *(float4*)&qs[gh][c4] =
            *(const float4*)(g_qkv + (size_t)n*QKVW + (h*GQH + gh)*DH + c4);
    }
    __syncthreads();

    if (tid < 65){
        const float4* kp = (tid == 0)
            ? (const float4*)(mem_kv + (size_t)h*DH)
            : (const float4*)(g_ckfull + (size_t)(h*65 + tid)*DH);
        float acc[8] = {0,0,0,0,0,0,0,0};
        #pragma unroll 8
        for (int dc = 0; dc < 32; dc++){
            float4 kv = kp[dc];
            #pragma unroll
            for (int gh = 0; gh < 8; gh++){
                float4 qv = *(const float4*)&qs[gh][dc*4];
                acc[gh] += qv.x*kv.x + qv.y*kv.y + qv.z*kv.z + qv.w*kv.w;
            }
        }
        #pragma unroll
        for (int gh = 0; gh < 8; gh++) s_l[gh][tid] = acc[gh] * SCALE;
    }
    __syncthreads();

    if (tid < 16){
        int f = tid;
        float s = 0.f;
        #pragma unroll
        for (int g = 0; g < 8; g++)
            #pragma unroll
            for (int w = 0; w < 4; w++) s += s_l[g][1 + f*4 + w];
        s *= (1.f / 32.f);
        if ((n >> 6) == f) s = NEGBIG;
        s_imp[f] = s;
    }
    __syncthreads();

    if (tid == 0){
        unsigned used = 0;
        int base = (h*NSEQ + n)*5;
        for (int r = 0; r < 4; r++){
            float best = -3.4e38f; int bi = 0;
            for (int f = 0; f < 16; f++)
                if (!((used >> f) & 1) && s_imp[f] > best){ best = s_imp[f]; bi = f; }
            used |= 1u << bi;
            g_sel[base + r] = bi;
        }
        g_sel[base + 4] = n >> 6;
    }

    float m = -3.4e38f;
    for (int j = lane; j < 65; j += 32) m = fmaxf(m, s_l[warp][j]);
    m = warp_max(m);
    float sum = 0.f;
    for (int j = lane; j < 65; j += 32){
        float e = __expf(s_l[warp][j] - m);
        s_l[warp][j] = e; sum += e;
    }
    sum = warp_sum(sum);
    float inv = 1.f / sum;

    float a0, a1, a2, a3;
    {
        float p = s_l[warp][0];
        float4 vv = *(const float4*)(mem_kv + (size_t)(KVH + h)*DH + lane*4);
        a0 = p*vv.x; a1 = p*vv.y; a2 = p*vv.z; a3 = p*vv.w;
    }
    #pragma unroll 4
    for (int j = 1; j < 65; j++){
        float p = s_l[warp][j];
        float4 vv = *(const float4*)(g_cvfull + (size_t)(h*65 + j)*DH + lane*4);
        a0 += p*vv.x; a1 += p*vv.y; a2 += p*vv.z; a3 += p*vv.w;
    }
    float* o = g_cmp + ((size_t)(h*GQH + warp)*NSEQ + n)*DH + lane*4;
    o[0] = a0*inv; o[1] = a1*inv; o[2] = a2*inv; o[3] = a3*inv;
}

// ---------------- fused fine + slide (R11 base + sP transpose for float4 AV) --
__global__ void fine_slide_kernel(){
    int n = blockIdx.x, h = blockIdx.y;
    int tid = threadIdx.x, warp = tid >> 5, lane = tid & 31;
    __shared__ __align__(16) float sT[8][320];     // [ghead][token]
    __shared__ __align__(16) float sP[320][8];     // [token][ghead] (post-softmax)
    __shared__ __align__(16) float qs[8][128];
    __shared__ int s_blk[5];

    if (blockIdx.z == 0 && tid < 5) s_blk[tid] = g_sel[(h*NSEQ + n)*5 + tid];
    {
        int gh = tid >> 5, c4 = (tid & 31)*4;
        *(float4*)&qs[gh][c4] =
            *(const float4*)(g_qrope + ((size_t)(h*GQH + gh)*NSEQ + n)*DH + c4);
    }
    __syncthreads();

    if (blockIdx.z == 0){
        // ---- fine: 320 tokens ----
        #pragma unroll
        for (int base = 0; base < 320; base += 256){
            int ti = base + tid;
            if (ti < 320){
                int tok = s_blk[ti >> 6]*64 + (ti & 63);
                const float4* kp = (const float4*)(g_krope + ((size_t)h*NSEQ + tok)*DH);
                float acc[8] = {0,0,0,0,0,0,0,0};
                #pragma unroll 8
                for (int dc = 0; dc < 32; dc++){
                    float4 kv = kp[dc];
                    #pragma unroll
                    for (int gh = 0; gh < 8; gh++){
                        float4 qv = *(const float4*)&qs[gh][dc*4];
                        acc[gh] += qv.x*kv.x + qv.y*kv.y + qv.z*kv.z + qv.w*kv.w;
                    }
                }
                #pragma unroll
                for (int gh = 0; gh < 8; gh++) sT[gh][ti] = acc[gh] * SCALE;
            }
        }
        __syncthreads();

        float m = -3.4e38f;
        for (int t = lane; t < 320; t += 32) m = fmaxf(m, sT[warp][t]);
        m = warp_max(m);
        float sum = 0.f;
        for (int t = lane; t < 320; t += 32){
            float e = __expf(sT[warp][t] - m);
            sT[warp][t] = e; sum += e;
        }
        sum = warp_sum(sum);
        float inv = 1.f / sum;
        for (int t = lane; t < 320; t += 32) sT[warp][t] *= inv;
        __syncthreads();

        // transpose normalized scores to sP[token][gh]
        #pragma unroll
        for (int i = 0; i < 10; i++){
            int idx = i*256 + tid;
            sP[idx >> 3][idx & 7] = sT[idx & 7][idx >> 3];
        }
        __syncthreads();

        int d = tid & 127, half = tid >> 7;
        int g0 = half*4;
        float a[4] = {0.f, 0.f, 0.f, 0.f};
        #pragma unroll
        for (int b = 0; b < 5; b++){
            size_t vbase = (size_t)s_blk[b]*64*QKVW + 2304 + h*DH + d;
            #pragma unroll 4
            for (int tt = 0; tt < 64; tt += 4){
                float v0 = g_qkv[vbase + (size_t)(tt+0)*QKVW];
                float v1 = g_qkv[vbase + (size_t)(tt+1)*QKVW];
                float v2 = g_qkv[vbase + (size_t)(tt+2)*QKVW];
                float v3 = g_qkv[vbase + (size_t)(tt+3)*QKVW];
                int t0 = b*64 + tt;
                float4 p0 = *(const float4*)&sP[t0+0][g0];
                float4 p1 = *(const float4*)&sP[t0+1][g0];
                float4 p2 = *(const float4*)&sP[t0+2][g0];
                float4 p3 = *(const float4*)&sP[t0+3][g0];
                a[0] += p0.x*v0 + p1.x*v1 + p2.x*v2 + p3.x*v3;
                a[1] += p0.y*v0 + p1.y*v1 + p2.y*v2 + p3.y*v3;
                a[2] += p0.z*v0 + p1.z*v1 + p2.z*v2 + p3.z*v3;
                a[3] += p0.w*v0 + p1.w*v1 + p2.w*v2 + p3.w*v3;
            }
        }
        #pragma unroll
        for (int gg = 0; gg < 4; gg++)
            g_fine[((size_t)(h*GQH + g0 + gg)*NSEQ + n)*DH + d] = a[gg];
    } else {
        // ---- slide: up to 257 tokens ----
        int lo = n - 128; if (lo < 0) lo = 0;
        int hi = n + 128; if (hi > NSEQ - 1) hi = NSEQ - 1;
        int cnt = hi - lo + 1;

        #pragma unroll
        for (int base = 0; base < 320; base += 256){
            int ti = base + tid;
            if (ti < cnt){
                const float4* kp = (const float4*)(g_krope + ((size_t)h*NSEQ + lo + ti)*DH);
                float acc[8] = {0,0,0,0,0,0,0,0};
                #pragma unroll 8
                for (int dc = 0; dc < 32; dc++){
                    float4 kv = kp[dc];
                    #pragma unroll
                    for (int gh = 0; gh < 8; gh++){
                        float4 qv = *(const float4*)&qs[gh][dc*4];
                        acc[gh] += qv.x*kv.x + qv.y*kv.y + qv.z*kv.z + qv.w*kv.w;
                    }
                }
                #pragma unroll
                for (int gh = 0; gh < 8; gh++) sT[gh][ti] = acc[gh] * SCALE;
            }
        }
        __syncthreads();

        float m = -3.4e38f;
        for (int t = lane; t < cnt; t += 32) m = fmaxf(m, sT[warp][t]);
        m = warp_max(m);
        float sum = 0.f;
        for (int t = lane; t < cnt; t += 32){
            float e = __expf(sT[warp][t] - m);
            sT[warp][t] = e; sum += e;
        }
        sum = warp_sum(sum);
        float inv = 1.f / sum;
        for (int t = lane; t < cnt; t += 32) sT[warp][t] *= inv;
        __syncthreads();

        // transpose normalized scores to sP[token][gh]
        for (int idx = tid; idx < cnt*8; idx += 256)
            sP[idx >> 3][idx & 7] = sT[idx & 7][idx >> 3];
        __syncthreads();

        int d = tid & 127, half = tid >> 7;
        int g0 = half*4;
        float a[4] = {0.f, 0.f, 0.f, 0.f};
        size_t vbase = (size_t)lo*QKVW + 2304 + h*DH + d;
        int cnt4 = cnt & ~3;
        #pragma unroll 4
        for (int tt = 0; tt < cnt4; tt += 4){
            float v0 = g_qkv[vbase + (size_t)(tt+0)*QKVW];
            float v1 = g_qkv[vbase + (size_t)(tt+1)*QKVW];
            float v2 = g_qkv[vbase + (size_t)(tt+2)*QKVW];
            float v3 = g_qkv[vbase + (size_t)(tt+3)*QKVW];
            float4 p0 = *(const float4*)&sP[tt+0][g0];
            float4 p1 = *(const float4*)&sP[tt+1][g0];
            float4 p2 = *(const float4*)&sP[tt+2][g0];
            float4 p3 = *(const float4*)&sP[tt+3][g0];
            a[0] += p0.x*v0 + p1.x*v1 + p2.x*v2 + p3.x*v3;
            a[1] += p0.y*v0 + p1.y*v1 + p2.y*v2 + p3.y*v3;
            a[2] += p0.z*v0 + p1.z*v1 + p2.z*v2 + p3.z*v3;
            a[3] += p0.w*v0 + p1.w*v1 + p2.w*v2 + p3.w*v3;
        }
        for (int tt = cnt4; tt < cnt; tt++){
            float v = g_qkv[vbase + (size_t)tt*QKVW];
            float4 p = *(const float4*)&sP[tt][g0];
            a[0] += p.x*v; a[1] += p.y*v; a[2] += p.z*v; a[3] += p.w*v;
        }
        #pragma unroll
        for (int gg = 0; gg < 4; gg++)
            g_slide[((size_t)(h*GQH + g0 + gg)*NSEQ + n)*DH + d] = a[gg];
    }
}

// ---------------- gate-weighted combine -> O1 A-frag (hi only) ----------------
__global__ void combine_kernel(const float* __restrict__ bg){
    int n = blockIdx.x, hq = blockIdx.y, d = threadIdx.x;
    __shared__ float sg[3];
    if (d < 3){
        float s = bg[hq*3 + d];
        #pragma unroll
        for (int p = 0; p < 16; p++)
            s += g_gpart[(size_t)p*NSEQ*48 + (size_t)n*48 + hq*3 + d];
        sg[d] = 1.f / (1.f + __expf(-s));
    }
    __syncthreads();
    float g0 = sg[0], g1 = sg[1], g2 = sg[2];
    size_t idx = ((size_t)hq*NSEQ + n)*DH + d;
    float o = g_cmp[idx]*g0 + g_fine[idx]*g1 + g_slide[idx]*g2;
    int k = hq*128 + d;
    int ks = k >> 3, mt = n >> 4;
    int lane = (n & 7)*4 + (k & 3);
    int slot = ((n >> 3) & 1) + 2*((k >> 2) & 1);
    ((float*)g_AOh)[(((size_t)ks*64 + mt)*32 + lane)*4 + slot] = tf32r(o);
}

// ---------------- launch ----------------
extern "C" void kernel_launch(void* const* d_in, const int* in_sizes, int n_in,
                              void* d_out, int out_size){
    const float* x      = (const float*)d_in[0];
    const float* g_norm = (const float*)d_in[1];
    const float* W_qkv  = (const float*)d_in[2];
    const float* k_pos  = (const float*)d_in[3];
    const float* v_pos  = (const float*)d_in[4];
    const float* mem_kv = (const float*)d_in[5];
    const float* Wk1    = (const float*)d_in[6];
    const float* bk1    = (const float*)d_in[7];
    const float* Wk2    = (const float*)d_in[8];
    const float* bk2    = (const float*)d_in[9];
    const float* Wv1    = (const float*)d_in[10];
    const float* bv1    = (const float*)d_in[11];
    const float* Wv2    = (const float*)d_in[12];
    const float* bv2    = (const float*)d_in[13];
    const float* Wg     = (const float*)d_in[14];
    const float* bg     = (const float*)d_in[15];
    const float* W_out  = (const float*)d_in[16];
    float* out = (float*)d_out;

    cudaFuncSetAttribute(gemm_tc<true>,  cudaFuncAttributeMaxDynamicSharedMemorySize, 98304);
    cudaFuncSetAttribute(gemm_tc<false>, cudaFuncAttributeMaxDynamicSharedMemorySize, 49152);
    cudaFuncSetAttribute(gemm_mlp1,      cudaFuncAttributeMaxDynamicSharedMemorySize, 65536);

    float4 *p_BFq, *p_AXh, *p_AXl, *p_AOh;
    float2 *p_BFo;
    float *p_qkv;
    cudaGetSymbolAddress((void**)&p_BFq,  g_BFq);
    cudaGetSymbolAddress((void**)&p_BFo,  g_BFo);
    cudaGetSymbolAddress((void**)&p_AXh,  g_AXh);
    cudaGetSymbolAddress((void**)&p_AXl,  g_AXl);
    cudaGetSymbolAddress((void**)&p_AOh,  g_AOh);
    cudaGetSymbolAddress((void**)&p_qkv,  g_qkv);

    // 0: rmsnorm + weight preps + rope table
    stage0_kernel<<<3584, 256>>>(x, g_norm, W_qkv, W_out);
    // 1: qkv = xn @ W_qkv (3xTF32)
    gemm_tc<true><<<dim3(QKVW/64, NSEQ/128), 256, 98304>>>(
        p_AXh, p_AXl, p_BFq, nullptr, p_qkv, 64, QKVW, XDIM, 0);
    // 2: build MLP inputs
    build_windows_kernel<<<4096, 256>>>(k_pos, v_pos);
    // 3 (ncu-captured): MLP1 k & v
    gemm_mlp1<<<dim3(CDIM/64, 2, 2), 256, 65536>>>(Wk1, Wv1, bk1, bv1);
    // 4: gates + rope
    gates_rope_kernel<<<4736, 256>>>(Wg);
    // 5: MLP2 -> ck/cv-full
    mlp2_kernel<<<128, 128>>>(Wk2, bk2, Wv2, bv2);
    // 6: compressed attention + selection (R11 form)
    cmp_attn_kernel<<<dim3(NSEQ, KVH), 256>>>(mem_kv);
    // 7: fine + slide (R11 form + float4 AV via sP transpose)
    fine_slide_kernel<<<dim3(NSEQ, KVH, 2), 256>>>();
    // 8: combine
    combine_kernel<<<dim3(NSEQ, NHEADS), 128>>>(bg);
    // 9: out = O1 @ W_out (plain TF32)
    gemm_tc<false><<<dim3(XDIM/64, NSEQ/128), 256, 49152>>>(
        p_AOh, nullptr, p_BFo, nullptr, out, 64, XDIM, XDIM, 0);
}

// round 17
// speedup vs baseline: 1.0832x; 1.0159x over previous
#include <cuda_runtime.h>
#include <math.h>
#include <stdint.h>

#define NSEQ   1024
#define XDIM   2048
#define NHEADS 16
#define KVH    2
#define GQH    8
#define DH     128
#define QKVW   2560      // 2048 + 256 + 256
#define CDIM   4096      // CMP_BLK * DH
#define SCALE  0.08838834764831845f
#define NEGBIG -1e10f

// ---------------- scratch (device globals; no runtime allocation) ----------------
__device__ __align__(128) float g_xn    [NSEQ*XDIM];
__device__ __align__(128) float g_qkv   [NSEQ*QKVW];
__device__ __align__(128) float g_hidden[2*128*CDIM];
__device__ __align__(128) float g_ckfull[KVH*65*DH];
__device__ __align__(128) float g_cvfull[KVH*65*DH];
__device__ __align__(128) float g_cmp   [NHEADS*NSEQ*DH];
__device__ __align__(128) float g_fine  [NHEADS*NSEQ*DH];
__device__ __align__(128) float g_slide [NHEADS*NSEQ*DH];
__device__ __align__(128) float g_qrope [NHEADS*NSEQ*DH];
__device__ __align__(128) float g_krope [KVH*NSEQ*DH];
__device__ __align__(128) float g_ropetab[NSEQ*64*2];
__device__ __align__(128) float g_gpart [16*NSEQ*48];
__device__ int g_sel[KVH*NSEQ*5];

// fragment-layout operand buffers
__device__ float4 g_BFq [256*320*32];       // W_qkv (split)
__device__ float2 g_BFo [256*256*32];       // W_out (plain)
__device__ float4 g_AXh[256*64*32],  g_AXl[256*64*32];    // xn
__device__ float4 g_AFh[2*512*8*32], g_AFl[2*512*8*32];   // compress-MLP inputs
__device__ float4 g_AOh[256*64*32];                       // combined O1 (hi only)

// ---------------- helpers ----------------
__device__ __forceinline__ float warp_sum(float v){
    #pragma unroll
    for (int o = 16; o > 0; o >>= 1) v += __shfl_xor_sync(0xffffffffu, v, o);
    return v;
}
__device__ __forceinline__ float warp_max(float v){
    #pragma unroll
    for (int o = 16; o > 0; o >>= 1) v = fmaxf(v, __shfl_xor_sync(0xffffffffu, v, o));
    return v;
}
__device__ __forceinline__ float tf32r(float x){
    unsigned r; asm("cvt.rna.tf32.f32 %0, %1;" : "=r"(r) : "f"(x));
    return __uint_as_float(r);
}
__device__ __forceinline__ void mma8(float* d, const unsigned* a, const unsigned* b){
    asm volatile("mma.sync.aligned.m16n8k8.row.col.f32.tf32.tf32.f32 "
        "{%0,%1,%2,%3},{%4,%5,%6,%7},{%8,%9},{%0,%1,%2,%3};"
        : "+f"(d[0]),"+f"(d[1]),"+f"(d[2]),"+f"(d[3])
        : "r"(a[0]),"r"(a[1]),"r"(a[2]),"r"(a[3]),"r"(b[0]),"r"(b[1]));
}
__device__ __forceinline__ void cp16(uint32_t s, const void* g){
    asm volatile("cp.async.cg.shared.global [%0], [%1], 16;" :: "r"(s), "l"(g));
}
__device__ __forceinline__ void cp8(uint32_t s, const void* g){
    asm volatile("cp.async.ca.shared.global [%0], [%1], 8;" :: "r"(s), "l"(g));
}
// packed f32x2 (Blackwell): 1 fma-slot does 2 FMAs
__device__ __forceinline__ unsigned long long pk2(float lo, float hi){
    unsigned long long r;
    asm("mov.b64 %0, {%1, %2};" : "=l"(r) : "f"(lo), "f"(hi));
    return r;
}
__device__ __forceinline__ void ffma2(unsigned long long& d,
                                      unsigned long long a, unsigned long long b){
    asm("fma.rn.f32x2 %0, %1, %2, %0;" : "+l"(d) : "l"(a), "l"(b));
}
__device__ __forceinline__ float2 upk2(unsigned long long v){
    float lo, hi;
    asm("mov.b64 {%0, %1}, %2;" : "=f"(lo), "=f"(hi) : "l"(v));
    return make_float2(lo, hi);
}
__device__ __forceinline__ void afrag_store(float* ph, float* pl, int M16,
                                            int row, int k, float v){
    int ks = k >> 3, mt = row >> 4;
    int lane = (row & 7)*4 + (k & 3);
    int slot = ((row >> 3) & 1) + 2*((k >> 2) & 1);
    size_t fi = (((size_t)ks*M16 + mt)*32 + lane)*4 + slot;
    float h = tf32r(v);
    ph[fi] = h;
    pl[fi] = tf32r(v - h);
}

// ---------------- weight prep bodies ----------------
__device__ __forceinline__ void prep4_body(const float* __restrict__ W,
                                           float4* __restrict__ BF, int N,
                                           int bx, int by, float (*sw)[65]){
    int n0 = bx*64, k0 = by*64;
    int t = threadIdx.x;
    #pragma unroll
    for (int ii = 0; ii < 4; ii++){
        int r = ii*16 + (t >> 4), c4 = (t & 15)*4;
        float4 v = *(const float4*)(W + (size_t)(k0 + r)*N + n0 + c4);
        sw[r][c4+0]=v.x; sw[r][c4+1]=v.y; sw[r][c4+2]=v.z; sw[r][c4+3]=v.w;
    }
    __syncthreads();
    int lane = t & 31, ct = t >> 5;
    int c = lane & 3, gcol = lane >> 2;
    #pragma unroll
    for (int i = 0; i < 8; i++){
        float v1 = sw[i*8 + c][ct*8 + gcol];
        float v2 = sw[i*8 + 4 + c][ct*8 + gcol];
        float h1 = tf32r(v1), l1 = tf32r(v1 - h1);
        float h2 = tf32r(v2), l2 = tf32r(v2 - h2);
        BF[((size_t)(k0/8 + i)*(N >> 3) + (n0 >> 3) + ct)*32 + lane] =
            make_float4(h1, h2, l1, l2);
    }
}
__device__ __forceinline__ void prep2_body(const float* __restrict__ W,
                                           float2* __restrict__ BF, int N,
                                           int bx, int by, float (*sw)[65]){
    int n0 = bx*64, k0 = by*64;
    int t = threadIdx.x;
    #pragma unroll
    for (int ii = 0; ii < 4; ii++){
        int r = ii*16 + (t >> 4), c4 = (t & 15)*4;
        float4 v = *(const float4*)(W + (size_t)(k0 + r)*N + n0 + c4);
        sw[r][c4+0]=v.x; sw[r][c4+1]=v.y; sw[r][c4+2]=v.z; sw[r][c4+3]=v.w;
    }
    __syncthreads();
    int lane = t & 31, ct = t >> 5;
    int c = lane & 3, gcol = lane >> 2;
    #pragma unroll
    for (int i = 0; i < 8; i++){
        float v1 = sw[i*8 + c][ct*8 + gcol];
        float v2 = sw[i*8 + 4 + c][ct*8 + gcol];
        BF[((size_t)(k0/8 + i)*(N >> 3) + (n0 >> 3) + ct)*32 + lane] =
            make_float2(tf32r(v1), tf32r(v2));
    }
}

// ---------------- fused stage0: rmsnorm + weight preps + rope table ----------
__global__ void stage0_kernel(const float* __restrict__ x, const float* __restrict__ g,
                              const float* __restrict__ Wq, const float* __restrict__ Wo){
    __shared__ float sw[64][65];
    int id = blockIdx.x;
    int tid = threadIdx.x;
    if (id < 1024){
        int n = id;
        const float4* row = (const float4*)(x + (size_t)n*XDIM);
        float s = 0.f;
        for (int i = tid; i < XDIM/4; i += 256){
            float4 v = row[i];
            s += v.x*v.x + v.y*v.y + v.z*v.z + v.w*v.w;
        }
        s = warp_sum(s);
        __shared__ float red[8];
        __shared__ float tot;
        if ((tid & 31) == 0) red[tid >> 5] = s;
        __syncthreads();
        if (tid < 32){
            float v = (tid < 8) ? red[tid] : 0.f;
            v = warp_sum(v);
            if (tid == 0) tot = rsqrtf(v / (float)XDIM + 1e-6f);
        }
        __syncthreads();
        float inv = tot;
        const float4* gg = (const float4*)g;
        float4* op = (float4*)(g_xn + (size_t)n*XDIM);
        float* ph = (float*)g_AXh;
        float* pl = (float*)g_AXl;
        for (int i = tid; i < XDIM/4; i += 256){
            float4 v = row[i], w = gg[i], o;
            o.x = v.x*inv*w.x; o.y = v.y*inv*w.y; o.z = v.z*inv*w.z; o.w = v.w*inv*w.w;
            op[i] = o;
            int k0 = i*4;
            afrag_store(ph, pl, 64, n, k0+0, o.x);
            afrag_store(ph, pl, 64, n, k0+1, o.y);
            afrag_store(ph, pl, 64, n, k0+2, o.z);
            afrag_store(ph, pl, 64, n, k0+3, o.w);
        }
        return;
    }
    id -= 1024;
    if (id < 1280){ prep4_body(Wq, g_BFq, QKVW, id % 40, id / 40, sw); return; }
    id -= 1280;
    if (id < 1024){ prep2_body(Wo, g_BFo, XDIM, id % 32, id / 32, sw); return; }
    id -= 1024;
    int idx = id * 256 + tid;
    int i = idx & 63, n = idx >> 6;
    double f = exp(-((double)(2*i) / 128.0) * 9.210340371976184);
    double ang = (double)n * f;
    g_ropetab[idx*2 + 0] = (float)cos(ang);
    g_ropetab[idx*2 + 1] = (float)sin(ang);
}

// ---------------- tensor-core GEMM (prepped B frags in gmem) ----------------
template<bool SPLIT>
__global__ __launch_bounds__(256)
void gemm_tc(const float4* __restrict__ AFh, const float4* __restrict__ AFl,
             const void* __restrict__ BFv,
             const float* __restrict__ bias,
             float* __restrict__ C,
             int M16, int N, int K, int relu){
    constexpr int MT16 = 8;
    constexpr int NT = 4;
    constexpr int APS = SPLIT ? 2 : 1;
    constexpr int SA_F4 = APS*4*MT16*32;
    constexpr int SB_EL = 4*8*32;

    extern __shared__ float4 smem[];
    char* sBraw = (char*)(smem + 2*SA_F4);

    int tid = threadIdx.x, lane = tid & 31, warp = tid >> 5;
    int bm16 = blockIdx.y*MT16;
    int bn8  = blockIdx.x*8;
    int wmi = warp & 3, wni = warp >> 2;
    int gid = lane >> 2, tig = lane & 3;
    int N8 = N >> 3;

    uint32_t sbase = (uint32_t)__cvta_generic_to_shared(smem);
    uint32_t sbB   = (uint32_t)__cvta_generic_to_shared(sBraw);

    float acc[2][NT][4];
    #pragma unroll
    for (int i = 0; i < 2; i++)
        #pragma unroll
        for (int j = 0; j < NT; j++)
            #pragma unroll
            for (int e = 0; e < 4; e++) acc[i][j][e] = 0.f;

    auto issue = [&](int ksl, int buf){
        #pragma unroll
        for (int i = 0; i < APS*4*MT16*32/256; i++){
            int idx = i*256 + tid;
            int l = idx & 31, q = idx >> 5;
            int mt = q % MT16, ks = (q/MT16) & 3, a = q/(MT16*4);
            const float4* src = (SPLIT && a ? AFl : AFh)
                + ((size_t)(ksl*4 + ks)*M16 + bm16 + mt)*32 + l;
            uint32_t dst = sbase + (uint32_t)(buf*SA_F4 + ((a*4+ks)*MT16+mt)*32+l)*16u;
            cp16(dst, src);
        }
        #pragma unroll
        for (int i = 0; i < 4; i++){
            int idx = i*256 + tid;
            int l = idx & 31, ct = (idx >> 5) & 7, ks = idx >> 8;
            size_t si = ((size_t)(ksl*4 + ks)*N8 + bn8 + ct)*32 + l;
            uint32_t dst = sbB + (uint32_t)(buf*SB_EL + (ks*8+ct)*32 + l)*(SPLIT?16u:8u);
            if (SPLIT) cp16(dst, (const float4*)BFv + si);
            else       cp8 (dst, (const float2*)BFv + si);
        }
        asm volatile("cp.async.commit_group;");
    };

    int nslab = K/32;
    issue(0, 0);
    int buf = 0;
    for (int ksl = 0; ksl < nslab; ksl++){
        asm volatile("cp.async.wait_group 0;");
        __syncthreads();
        if (ksl + 1 < nslab) issue(ksl + 1, buf ^ 1);
        #pragma unroll
        for (int ks = 0; ks < 4; ks++){
            uint4 ah[2], al[2];
            #pragma unroll
            for (int mt = 0; mt < 2; mt++){
                int mtt = wmi*2 + mt;
                ah[mt] = *(const uint4*)&smem[buf*SA_F4 + ((0*4+ks)*MT16+mtt)*32 + lane];
                if (SPLIT)
                    al[mt] = *(const uint4*)&smem[buf*SA_F4 + ((1*4+ks)*MT16+mtt)*32 + lane];
            }
            #pragma unroll
            for (int nt = 0; nt < NT; nt++){
                int bi = (ks*8 + wni*NT + nt)*32 + lane;
                unsigned bh[2], bl[2];
                if (SPLIT){
                    float4 bf = ((const float4*)sBraw)[buf*SB_EL + bi];
                    bh[0]=__float_as_uint(bf.x); bh[1]=__float_as_uint(bf.y);
                    bl[0]=__float_as_uint(bf.z); bl[1]=__float_as_uint(bf.w);
                } else {
                    float2 bf = ((const float2*)sBraw)[buf*SB_EL + bi];
                    bh[0]=__float_as_uint(bf.x); bh[1]=__float_as_uint(bf.y);
                }
                #pragma unroll
                for (int mt = 0; mt < 2; mt++){
                    if (SPLIT){
                        mma8(acc[mt][nt], (const unsigned*)&ah[mt], bl);
                        mma8(acc[mt][nt], (const unsigned*)&al[mt], bh);
                    }
                    mma8(acc[mt][nt], (const unsigned*)&ah[mt], bh);
                }
            }
        }
        buf ^= 1;
    }

    #pragma unroll
    for (int mt = 0; mt < 2; mt++){
        int row = (bm16 + wmi*2 + mt)*16 + gid;
        #pragma unroll
        for (int nt = 0; nt < NT; nt++){
            int col = (bn8 + wni*NT + nt)*8 + tig*2;
            float b0 = bias ? bias[col]   : 0.f;
            float b1 = bias ? bias[col+1] : 0.f;
            float d0 = acc[mt][nt][0] + b0, d1 = acc[mt][nt][1] + b1;
            float d2 = acc[mt][nt][2] + b0, d3 = acc[mt][nt][3] + b1;
            if (relu){
                d0 = fmaxf(d0, 0.f); d1 = fmaxf(d1, 0.f);
                d2 = fmaxf(d2, 0.f); d3 = fmaxf(d3, 0.f);
            }
            *(float2*)(C + (size_t)row*N + col)     = make_float2(d0, d1);
            *(float2*)(C + (size_t)(row+8)*N + col) = make_float2(d2, d3);
        }
    }
}

// ---------------- MLP1 GEMM: BM=64, raw B weights, in-kernel split conversion --
__global__ __launch_bounds__(256)
void gemm_mlp1(const float* __restrict__ Wk1, const float* __restrict__ Wv1,
               const float* __restrict__ bk1, const float* __restrict__ bv1){
    constexpr int NT = 2;
    constexpr int SA_F4 = 2*4*4*32;
    extern __shared__ float4 smem[];
    float* sRaw  = (float*)(smem + 2*SA_F4);
    float4* sBF  = (float4*)(sRaw + 2*32*64);

    const float* W    = blockIdx.z ? Wv1 : Wk1;
    const float* bias = blockIdx.z ? bv1 : bk1;
    const float4* AFh = g_AFh + (size_t)blockIdx.z*512*8*32;
    const float4* AFl = g_AFl + (size_t)blockIdx.z*512*8*32;
    float* C = g_hidden + (size_t)blockIdx.z*128*CDIM;

    int tid = threadIdx.x, lane = tid & 31, warp = tid >> 5;
    int bn = blockIdx.x*64;
    int bm16 = blockIdx.y*4;
    int wmi = warp & 1, wni = warp >> 1;
    int gid = lane >> 2, tig = lane & 3;

    uint32_t sbase = (uint32_t)__cvta_generic_to_shared(smem);
    uint32_t sbRaw = (uint32_t)__cvta_generic_to_shared(sRaw);

    float acc[2][NT][4];
    #pragma unroll
    for (int i = 0; i < 2; i++)
        #pragma unroll
        for (int j = 0; j < NT; j++)
            #pragma unroll
            for (int e = 0; e < 4; e++) acc[i][j][e] = 0.f;

    auto issue = [&](int ksl, int buf){
        #pragma unroll
        for (int i = 0; i < 4; i++){
            int idx = i*256 + tid;
            int l = idx & 31, q = idx >> 5;
            int mt = q & 3, ks = (q >> 2) & 3, a = q >> 4;
            const float4* src = (a ? AFl : AFh)
                + ((size_t)(ksl*4 + ks)*8 + bm16 + mt)*32 + l;
            uint32_t dst = sbase + (uint32_t)(buf*SA_F4 + ((a*4+ks)*4+mt)*32+l)*16u;
            cp16(dst, src);
        }
        #pragma unroll
        for (int i = 0; i < 2; i++){
            int idx = i*256 + tid;
            int k = idx >> 4, nq = (idx & 15)*4;
            int pn = nq ^ ((k & 3) << 3);
            const float* src = W + (size_t)(ksl*32 + k)*CDIM + bn + nq;
            uint32_t dst = sbRaw + (uint32_t)(buf*2048 + k*64 + pn)*4u;
            cp16(dst, src);
        }
        asm volatile("cp.async.commit_group;");
    };

    issue(0, 0);
    int buf = 0;
    for (int ksl = 0; ksl < 128; ksl++){
        asm volatile("cp.async.wait_group 0;");
        __syncthreads();
        if (ksl + 1 < 128) issue(ksl + 1, buf ^ 1);
        {
            const float* rb = sRaw + buf*2048;
            #pragma unroll
            for (int i = 0; i < 4; i++){
                int fi = i*256 + tid;
                int l = fi & 31, q = fi >> 5;
                int ct = q & 7, ks = q >> 3;
                int k1 = ks*8 + (l & 3);
                int n  = ct*8 + (l >> 2);
                float v1 = rb[k1*64 + (n ^ ((k1 & 3) << 3))];
                int k2 = k1 + 4;
                float v2 = rb[k2*64 + (n ^ ((k2 & 3) << 3))];
                float h1 = tf32r(v1), l1 = tf32r(v1 - h1);
                float h2 = tf32r(v2), l2 = tf32r(v2 - h2);
                sBF[(ks*8 + ct)*32 + l] = make_float4(h1, h2, l1, l2);
            }
        }
        __syncthreads();
        #pragma unroll
        for (int ks = 0; ks < 4; ks++){
            uint4 ah[2], al[2];
            #pragma unroll
            for (int mt = 0; mt < 2; mt++){
                int mtt = wmi*2 + mt;
                ah[mt] = *(const uint4*)&smem[buf*SA_F4 + ((0*4+ks)*4+mtt)*32 + lane];
                al[mt] = *(const uint4*)&smem[buf*SA_F4 + ((1*4+ks)*4+mtt)*32 + lane];
            }
            #pragma unroll
            for (int nt = 0; nt < NT; nt++){
                float4 bf = sBF[(ks*8 + wni*NT + nt)*32 + lane];
                unsigned bh[2] = {__float_as_uint(bf.x), __float_as_uint(bf.y)};
                unsigned bl[2] = {__float_as_uint(bf.z), __float_as_uint(bf.w)};
                #pragma unroll
                for (int mt = 0; mt < 2; mt++){
                    mma8(acc[mt][nt], (const unsigned*)&ah[mt], bl);
                    mma8(acc[mt][nt], (const unsigned*)&al[mt], bh);
                    mma8(acc[mt][nt], (const unsigned*)&ah[mt], bh);
                }
            }
        }
        buf ^= 1;
    }

    #pragma unroll
    for (int mt = 0; mt < 2; mt++){
        int row = (bm16 + wmi*2 + mt)*16 + gid;
        #pragma unroll
        for (int nt = 0; nt < NT; nt++){
            int col = bn + (wni*NT + nt)*8 + tig*2;
            float d0 = fmaxf(acc[mt][nt][0] + bias[col],   0.f);
            float d1 = fmaxf(acc[mt][nt][1] + bias[col+1], 0.f);
            float d2 = fmaxf(acc[mt][nt][2] + bias[col],   0.f);
            float d3 = fmaxf(acc[mt][nt][3] + bias[col+1], 0.f);
            *(float2*)(C + (size_t)row*CDIM + col)     = make_float2(d0, d1);
            *(float2*)(C + (size_t)(row+8)*CDIM + col) = make_float2(d2, d3);
        }
    }
}

// ---------------- build compressed-window MLP inputs (direct to A-frag) -------
__global__ void build_windows_kernel(const float* __restrict__ k_pos,
                                     const float* __restrict__ v_pos){
    int idx = blockIdx.x * 256 + threadIdx.x;
    int d = idx & 127;
    int j = (idx >> 7) & 31;
    int w = (idx >> 12) & 63;
    int h = (idx >> 18) & 1;
    int s = (idx >> 19) & 1;
    int t = w*16 + j - 16;
    const float* pos = s ? v_pos : k_pos;
    float pv = pos[(h*32 + j)*128 + d];
    float val = 0.f;
    if (t >= 0) val = g_qkv[(size_t)t*QKVW + (s ? 2304 : 2048) + h*128 + d];
    float v = val + pv;
    int row = h*64 + w;
    int k   = j*128 + d;
    float* ph = (float*)(g_AFh + (size_t)s*512*8*32);
    float* pl = (float*)(g_AFl + (size_t)s*512*8*32);
    afrag_store(ph, pl, 8, row, k, v);
}

// ---------------- fused gates + rope (after qkv) ----------
__global__ void gates_rope_kernel(const float* __restrict__ Wg){
    __shared__ float s_a[128][17];
    __shared__ float s_b[16][48];
    int id = blockIdx.x;
    int t = threadIdx.x;
    if (id < 128){
        int ks = id & 15, bm = (id >> 4) * 128;
        int rg = t >> 3, cg = t & 7;
        float acc[4][6];
        #pragma unroll
        for (int i = 0; i < 4; i++)
            #pragma unroll
            for (int j = 0; j < 6; j++) acc[i][j] = 0.f;
        int k0base = ks * 128;
        for (int kk = 0; kk < 128; kk += 16){
            int row = t >> 1, kh = (t & 1) * 8;
            const float* src = g_xn + (size_t)(bm + row)*XDIM + k0base + kk + kh;
            float4 v0 = *(const float4*)src, v1 = *(const float4*)(src + 4);
            s_a[row][kh+0]=v0.x; s_a[row][kh+1]=v0.y; s_a[row][kh+2]=v0.z; s_a[row][kh+3]=v0.w;
            s_a[row][kh+4]=v1.x; s_a[row][kh+5]=v1.y; s_a[row][kh+6]=v1.z; s_a[row][kh+7]=v1.w;
            #pragma unroll
            for (int i = 0; i < 3; i++){
                int idx = i*256 + t;
                s_b[idx/48][idx%48] = Wg[(size_t)(k0base + kk + idx/48)*48 + idx%48];
            }
            __syncthreads();
            #pragma unroll 4
            for (int k = 0; k < 16; k++){
                float a[4], b[6];
                #pragma unroll
                for (int i = 0; i < 4; i++) a[i] = s_a[rg*4 + i][k];
                #pragma unroll
                for (int j = 0; j < 6; j++) b[j] = s_b[k][cg*6 + j];
                #pragma unroll
                for (int i = 0; i < 4; i++)
                    #pragma unroll
                    for (int j = 0; j < 6; j++) acc[i][j] += a[i]*b[j];
            }
            __syncthreads();
        }
        #pragma unroll
        for (int i = 0; i < 4; i++)
            #pragma unroll
            for (int j = 0; j < 6; j++)
                g_gpart[(size_t)ks*NSEQ*48 + (size_t)(bm + rg*4 + i)*48 + cg*6 + j] = acc[i][j];
        return;
    }
    id -= 128;
    int p = id*4 + (t >> 6);
    int i = t & 63;
    int hh = p >> 10, n = p & 1023;
    float c = g_ropetab[(n*64 + i)*2 + 0];
    float s = g_ropetab[(n*64 + i)*2 + 1];
    const float* src; float* dst;
    if (hh < 16){
        src = g_qkv + (size_t)n*QKVW + hh*DH;
        dst = g_qrope + ((size_t)hh*NSEQ + n)*DH;
    } else {
        int h = hh - 16;
        src = g_qkv + (size_t)n*QKVW + 2048 + h*DH;
        dst = g_krope + ((size_t)h*NSEQ + n)*DH;
    }
    float x1 = src[2*i], x2 = src[2*i + 1];
    dst[2*i]     = x1*c - x2*s;
    dst[2*i + 1] = x1*s + x2*c;
}

// ---------------- MLP2: 128 blocks x 2 rows; writes ck/cv-full at j+1 --------
__global__ void mlp2_kernel(const float* __restrict__ Wk2, const float* __restrict__ bk2,
                            const float* __restrict__ Wv2, const float* __restrict__ bv2){
    int r0 = blockIdx.x * 2;
    int c  = threadIdx.x;
    const float* B    = (r0 < 128) ? Wk2 : Wv2;
    const float* bias = (r0 < 128) ? bk2 : bv2;
    __shared__ __align__(16) float s_a[2][1024];
    float acc[2] = {0.f, 0.f};
    for (int kc = 0; kc < 4096; kc += 1024){
        #pragma unroll
        for (int i = 0; i < 4; i++){
            int idx = i*128 + threadIdx.x;
            int rr = idx >> 8, cc = idx & 255;
            float4 v = *((const float4*)(g_hidden + (size_t)(r0 + rr)*4096 + kc) + cc);
            *((float4*)&s_a[rr][cc*4]) = v;
        }
        __syncthreads();
        #pragma unroll 4
        for (int k = 0; k < 1024; k++){
            float b = B[(size_t)(kc + k)*128 + c];
            acc[0] += s_a[0][k]*b; acc[1] += s_a[1][k]*b;
        }
        __syncthreads();
    }
    #pragma unroll
    for (int i = 0; i < 2; i++){
        int r = r0 + i;
        int s = r >> 7, rr = r & 127, h = rr >> 6, w = rr & 63;
        float* dst = s ? g_cvfull : g_ckfull;
        dst[(h*65 + 1 + w)*128 + c] = acc[i] + bias[c];
    }
}

// ---------------- compressed attention: thread-per-token QK, f32x2 ----------
__global__ void cmp_attn_kernel(const float* __restrict__ mem_kv){
    int n = blockIdx.x, h = blockIdx.y;
    int tid = threadIdx.x, warp = tid >> 5, lane = tid & 31;
    __shared__ float s_l[8][65];
    __shared__ float s_imp[16];
    __shared__ __align__(16) float qs[8][128];

    {
        int gh = tid >> 5, c4 = (tid & 31)*4;
        *(float4*)&qs[gh][c4] =
            *(const float4*)(g_qkv + (size_t)n*QKVW + (h*GQH + gh)*DH + c4);
    }
    __syncthreads();

    if (tid < 65){
        const float4* kp = (tid == 0)
            ? (const float4*)(mem_kv + (size_t)h*DH)
            : (const float4*)(g_ckfull + (size_t)(h*65 + tid)*DH);
        unsigned long long acc2[8] = {0,0,0,0,0,0,0,0};
        #pragma unroll 8
        for (int dc = 0; dc < 32; dc++){
            float4 kv = kp[dc];
            unsigned long long k01 = pk2(kv.x, kv.y), k23 = pk2(kv.z, kv.w);
            #pragma unroll
            for (int gh = 0; gh < 8; gh++){
                float4 qv = *(const float4*)&qs[gh][dc*4];
                ffma2(acc2[gh], pk2(qv.x, qv.y), k01);
                ffma2(acc2[gh], pk2(qv.z, qv.w), k23);
            }
        }
        #pragma unroll
        for (int gh = 0; gh < 8; gh++){
            float2 pr = upk2(acc2[gh]);
            s_l[gh][tid] = (pr.x + pr.y) * SCALE;
        }
    }
    __syncthreads();

    if (tid < 16){
        int f = tid;
        float s = 0.f;
        #pragma unroll
        for (int g = 0; g < 8; g++)
            #pragma unroll
            for (int w = 0; w < 4; w++) s += s_l[g][1 + f*4 + w];
        s *= (1.f / 32.f);
        if ((n >> 6) == f) s = NEGBIG;
        s_imp[f] = s;
    }
    __syncthreads();

    if (tid == 0){
        unsigned used = 0;
        int base = (h*NSEQ + n)*5;
        for (int r = 0; r < 4; r++){
            float best = -3.4e38f; int bi = 0;
            for (int f = 0; f < 16; f++)
                if (!((used >> f) & 1) && s_imp[f] > best){ best = s_imp[f]; bi = f; }
            used |= 1u << bi;
            g_sel[base + r] = bi;
        }
        g_sel[base + 4] = n >> 6;
    }

    float m = -3.4e38f;
    for (int j = lane; j < 65; j += 32) m = fmaxf(m, s_l[warp][j]);
    m = warp_max(m);
    float sum = 0.f;
    for (int j = lane; j < 65; j += 32){
        float e = __expf(s_l[warp][j] - m);
        s_l[warp][j] = e; sum += e;
    }
    sum = warp_sum(sum);
    float inv = 1.f / sum;

    unsigned long long a2lo = 0, a2hi = 0;   // {a0,a1}, {a2,a3}
    {
        float p = s_l[warp][0];
        float4 vv = *(const float4*)(mem_kv + (size_t)(KVH + h)*DH + lane*4);
        unsigned long long pp = pk2(p, p);
        ffma2(a2lo, pk2(vv.x, vv.y), pp);
        ffma2(a2hi, pk2(vv.z, vv.w), pp);
    }
    #pragma unroll 4
    for (int j = 1; j < 65; j++){
        float p = s_l[warp][j];
        float4 vv = *(const float4*)(g_cvfull + (size_t)(h*65 + j)*DH + lane*4);
        unsigned long long pp = pk2(p, p);
        ffma2(a2lo, pk2(vv.x, vv.y), pp);
        ffma2(a2hi, pk2(vv.z, vv.w), pp);
    }
    float2 alo = upk2(a2lo), ahi = upk2(a2hi);
    float* o = g_cmp + ((size_t)(h*GQH + warp)*NSEQ + n)*DH + lane*4;
    o[0] = alo.x*inv; o[1] = alo.y*inv; o[2] = ahi.x*inv; o[3] = ahi.y*inv;
}

// ---------------- fused fine + slide (sP transpose + f32x2) -------------------
__global__ void fine_slide_kernel(){
    int n = blockIdx.x, h = blockIdx.y;
    int tid = threadIdx.x, warp = tid >> 5, lane = tid & 31;
    __shared__ __align__(16) float sT[8][320];     // [ghead][token]
    __shared__ __align__(16) float sP[320][8];     // [token][ghead] (post-softmax)
    __shared__ __align__(16) float qs[8][128];
    __shared__ int s_blk[5];

    if (blockIdx.z == 0 && tid < 5) s_blk[tid] = g_sel[(h*NSEQ + n)*5 + tid];
    {
        int gh = tid >> 5, c4 = (tid & 31)*4;
        *(float4*)&qs[gh][c4] =
            *(const float4*)(g_qrope + ((size_t)(h*GQH + gh)*NSEQ + n)*DH + c4);
    }
    __syncthreads();

    if (blockIdx.z == 0){
        // ---- fine: 320 tokens ----
        #pragma unroll
        for (int base = 0; base < 320; base += 256){
            int ti = base + tid;
            if (ti < 320){
                int tok = s_blk[ti >> 6]*64 + (ti & 63);
                const float4* kp = (const float4*)(g_krope + ((size_t)h*NSEQ + tok)*DH);
                unsigned long long acc2[8] = {0,0,0,0,0,0,0,0};
                #pragma unroll 8
                for (int dc = 0; dc < 32; dc++){
                    float4 kv = kp[dc];
                    unsigned long long k01 = pk2(kv.x, kv.y), k23 = pk2(kv.z, kv.w);
                    #pragma unroll
                    for (int gh = 0; gh < 8; gh++){
                        float4 qv = *(const float4*)&qs[gh][dc*4];
                        ffma2(acc2[gh], pk2(qv.x, qv.y), k01);
                        ffma2(acc2[gh], pk2(qv.z, qv.w), k23);
                    }
                }
                #pragma unroll
                for (int gh = 0; gh < 8; gh++){
                    float2 pr = upk2(acc2[gh]);
                    sT[gh][ti] = (pr.x + pr.y) * SCALE;
                }
            }
        }
        __syncthreads();

        float m = -3.4e38f;
        for (int t = lane; t < 320; t += 32) m = fmaxf(m, sT[warp][t]);
        m = warp_max(m);
        float sum = 0.f;
        for (int t = lane; t < 320; t += 32){
            float e = __expf(sT[warp][t] - m);
            sT[warp][t] = e; sum += e;
        }
        sum = warp_sum(sum);
        float inv = 1.f / sum;
        for (int t = lane; t < 320; t += 32) sT[warp][t] *= inv;
        __syncthreads();

        #pragma unroll
        for (int i = 0; i < 10; i++){
            int idx = i*256 + tid;
            sP[idx >> 3][idx & 7] = sT[idx & 7][idx >> 3];
        }
        __syncthreads();

        int d = tid & 127, half = tid >> 7;
        int g0 = half*4;
        unsigned long long a2lo = 0, a2hi = 0;   // {a0,a1},{a2,a3}
        #pragma unroll
        for (int b = 0; b < 5; b++){
            size_t vbase = (size_t)s_blk[b]*64*QKVW + 2304 + h*DH + d;
            #pragma unroll 4
            for (int tt = 0; tt < 64; tt += 4){
                float v0 = g_qkv[vbase + (size_t)(tt+0)*QKVW];
                float v1 = g_qkv[vbase + (size_t)(tt+1)*QKVW];
                float v2 = g_qkv[vbase + (size_t)(tt+2)*QKVW];
                float v3 = g_qkv[vbase + (size_t)(tt+3)*QKVW];
                int t0 = b*64 + tt;
                float4 p0 = *(const float4*)&sP[t0+0][g0];
                float4 p1 = *(const float4*)&sP[t0+1][g0];
                float4 p2 = *(const float4*)&sP[t0+2][g0];
                float4 p3 = *(const float4*)&sP[t0+3][g0];
                unsigned long long vv0 = pk2(v0, v0), vv1 = pk2(v1, v1);
                unsigned long long vv2 = pk2(v2, v2), vv3 = pk2(v3, v3);
                ffma2(a2lo, pk2(p0.x, p0.y), vv0);
                ffma2(a2hi, pk2(p0.z, p0.w), vv0);
                ffma2(a2lo, pk2(p1.x, p1.y), vv1);
                ffma2(a2hi, pk2(p1.z, p1.w), vv1);
                ffma2(a2lo, pk2(p2.x, p2.y), vv2);
                ffma2(a2hi, pk2(p2.z, p2.w), vv2);
                ffma2(a2lo, pk2(p3.x, p3.y), vv3);
                ffma2(a2hi, pk2(p3.z, p3.w), vv3);
            }
        }
        float2 alo = upk2(a2lo), ahi = upk2(a2hi);
        g_fine[((size_t)(h*GQH + g0 + 0)*NSEQ + n)*DH + d] = alo.x;
        g_fine[((size_t)(h*GQH + g0 + 1)*NSEQ + n)*DH + d] = alo.y;
        g_fine[((size_t)(h*GQH + g0 + 2)*NSEQ + n)*DH + d] = ahi.x;
        g_fine[((size_t)(h*GQH + g0 + 3)*NSEQ + n)*DH + d] = ahi.y;
    } else {
        // ---- slide: up to 257 tokens ----
        int lo = n - 128; if (lo < 0) lo = 0;
        int hi = n + 128; if (hi > NSEQ - 1) hi = NSEQ - 1;
        int cnt = hi - lo + 1;

        #pragma unroll
        for (int base = 0; base < 320; base += 256){
            int ti = base + tid;
            if (ti < cnt){
                const float4* kp = (const float4*)(g_krope + ((size_t)h*NSEQ + lo + ti)*DH);
                unsigned long long acc2[8] = {0,0,0,0,0,0,0,0};
                #pragma unroll 8
                for (int dc = 0; dc < 32; dc++){
                    float4 kv = kp[dc];
                    unsigned long long k01 = pk2(kv.x, kv.y), k23 = pk2(kv.z, kv.w);
                    #pragma unroll
                    for (int gh = 0; gh < 8; gh++){
                        float4 qv = *(const float4*)&qs[gh][dc*4];
                        ffma2(acc2[gh], pk2(qv.x, qv.y), k01);
                        ffma2(acc2[gh], pk2(qv.z, qv.w), k23);
                    }
                }
                #pragma unroll
                for (int gh = 0; gh < 8; gh++){
                    float2 pr = upk2(acc2[gh]);
                    sT[gh][ti] = (pr.x + pr.y) * SCALE;
                }
            }
        }
        __syncthreads();

        float m = -3.4e38f;
        for (int t = lane; t < cnt; t += 32) m = fmaxf(m, sT[warp][t]);
        m = warp_max(m);
        float sum = 0.f;
        for (int t = lane; t < cnt; t += 32){
            float e = __expf(sT[warp][t] - m);
            sT[warp][t] = e; sum += e;
        }
        sum = warp_sum(sum);
        float inv = 1.f / sum;
        for (int t = lane; t < cnt; t += 32) sT[warp][t] *= inv;
        __syncthreads();

        for (int idx = tid; idx < cnt*8; idx += 256)
            sP[idx >> 3][idx & 7] = sT[idx & 7][idx >> 3];
        __syncthreads();

        int d = tid & 127, half = tid >> 7;
        int g0 = half*4;
        unsigned long long a2lo = 0, a2hi = 0;
        size_t vbase = (size_t)lo*QKVW + 2304 + h*DH + d;
        int cnt4 = cnt & ~3;
        #pragma unroll 4
        for (int tt = 0; tt < cnt4; tt += 4){
            float v0 = g_qkv[vbase + (size_t)(tt+0)*QKVW];
            float v1 = g_qkv[vbase + (size_t)(tt+1)*QKVW];
            float v2 = g_qkv[vbase + (size_t)(tt+2)*QKVW];
            float v3 = g_qkv[vbase + (size_t)(tt+3)*QKVW];
            float4 p0 = *(const float4*)&sP[tt+0][g0];
            float4 p1 = *(const float4*)&sP[tt+1][g0];
            float4 p2 = *(const float4*)&sP[tt+2][g0];
            float4 p3 = *(const float4*)&sP[tt+3][g0];
            unsigned long long vv0 = pk2(v0, v0), vv1 = pk2(v1, v1);
            unsigned long long vv2 = pk2(v2, v2), vv3 = pk2(v3, v3);
            ffma2(a2lo, pk2(p0.x, p0.y), vv0);
            ffma2(a2hi, pk2(p0.z, p0.w), vv0);
            ffma2(a2lo, pk2(p1.x, p1.y), vv1);
            ffma2(a2hi, pk2(p1.z, p1.w), vv1);
            ffma2(a2lo, pk2(p2.x, p2.y), vv2);
            ffma2(a2hi, pk2(p2.z, p2.w), vv2);
            ffma2(a2lo, pk2(p3.x, p3.y), vv3);
            ffma2(a2hi, pk2(p3.z, p3.w), vv3);
        }
        for (int tt = cnt4; tt < cnt; tt++){
            float v = g_qkv[vbase + (size_t)tt*QKVW];
            float4 p = *(const float4*)&sP[tt][g0];
            unsigned long long vv = pk2(v, v);
            ffma2(a2lo, pk2(p.x, p.y), vv);
            ffma2(a2hi, pk2(p.z, p.w), vv);
        }
        float2 alo = upk2(a2lo), ahi = upk2(a2hi);
        g_slide[((size_t)(h*GQH + g0 + 0)*NSEQ + n)*DH + d] = alo.x;
        g_slide[((size_t)(h*GQH + g0 + 1)*NSEQ + n)*DH + d] = alo.y;
        g_slide[((size_t)(h*GQH + g0 + 2)*NSEQ + n)*DH + d] = ahi.x;
        g_slide[((size_t)(h*GQH + g0 + 3)*NSEQ + n)*DH + d] = ahi.y;
    }
}

// ---------------- gate-weighted combine -> O1 A-frag (hi only) ----------------
__global__ void combine_kernel(const float* __restrict__ bg){
    int n = blockIdx.x, hq = blockIdx.y, d = threadIdx.x;
    __shared__ float sg[3];
    if (d < 3){
        float s = bg[hq*3 + d];
        #pragma unroll
        for (int p = 0; p < 16; p++)
            s += g_gpart[(size_t)p*NSEQ*48 + (size_t)n*48 + hq*3 + d];
        sg[d] = 1.f / (1.f + __expf(-s));
    }
    __syncthreads();
    float g0 = sg[0], g1 = sg[1], g2 = sg[2];
    size_t idx = ((size_t)hq*NSEQ + n)*DH + d;
    float o = g_cmp[idx]*g0 + g_fine[idx]*g1 + g_slide[idx]*g2;
    int k = hq*128 + d;
    int ks = k >> 3, mt = n >> 4;
    int lane = (n & 7)*4 + (k & 3);
    int slot = ((n >> 3) & 1) + 2*((k >> 2) & 1);
    ((float*)g_AOh)[(((size_t)ks*64 + mt)*32 + lane)*4 + slot] = tf32r(o);
}

// ---------------- launch ----------------
extern "C" void kernel_launch(void* const* d_in, const int* in_sizes, int n_in,
                              void* d_out, int out_size){
    const float* x      = (const float*)d_in[0];
    const float* g_norm = (const float*)d_in[1];
    const float* W_qkv  = (const float*)d_in[2];
    const float* k_pos  = (const float*)d_in[3];
    const float* v_pos  = (const float*)d_in[4];
    const float* mem_kv = (const float*)d_in[5];
    const float* Wk1    = (const float*)d_in[6];
    const float* bk1    = (const float*)d_in[7];
    const float* Wk2    = (const float*)d_in[8];
    const float* bk2    = (const float*)d_in[9];
    const float* Wv1    = (const float*)d_in[10];
    const float* bv1    = (const float*)d_in[11];
    const float* Wv2    = (const float*)d_in[12];
    const float* bv2    = (const float*)d_in[13];
    const float* Wg     = (const float*)d_in[14];
    const float* bg     = (const float*)d_in[15];
    const float* W_out  = (const float*)d_in[16];
    float* out = (float*)d_out;

    cudaFuncSetAttribute(gemm_tc<true>,  cudaFuncAttributeMaxDynamicSharedMemorySize, 98304);
    cudaFuncSetAttribute(gemm_tc<false>, cudaFuncAttributeMaxDynamicSharedMemorySize, 49152);
    cudaFuncSetAttribute(gemm_mlp1,      cudaFuncAttributeMaxDynamicSharedMemorySize, 65536);

    float4 *p_BFq, *p_AXh, *p_AXl, *p_AOh;
    float2 *p_BFo;
    float *p_qkv;
    cudaGetSymbolAddress((void**)&p_BFq,  g_BFq);
    cudaGetSymbolAddress((void**)&p_BFo,  g_BFo);
    cudaGetSymbolAddress((void**)&p_AXh,  g_AXh);
    cudaGetSymbolAddress((void**)&p_AXl,  g_AXl);
    cudaGetSymbolAddress((void**)&p_AOh,  g_AOh);
    cudaGetSymbolAddress((void**)&p_qkv,  g_qkv);

    // 0: rmsnorm + weight preps + rope table
    stage0_kernel<<<3584, 256>>>(x, g_norm, W_qkv, W_out);
    // 1: qkv = xn @ W_qkv (3xTF32)
    gemm_tc<true><<<dim3(QKVW/64, NSEQ/128), 256, 98304>>>(
        p_AXh, p_AXl, p_BFq, nullptr, p_qkv, 64, QKVW, XDIM, 0);
    // 2: build MLP inputs
    build_windows_kernel<<<4096, 256>>>(k_pos, v_pos);
    // 3 (ncu-captured): MLP1 k & v
    gemm_mlp1<<<dim3(CDIM/64, 2, 2), 256, 65536>>>(Wk1, Wv1, bk1, bv1);
    // 4: gates + rope
    gates_rope_kernel<<<4736, 256>>>(Wg);
    // 5: MLP2 -> ck/cv-full
    mlp2_kernel<<<128, 128>>>(Wk2, bk2, Wv2, bv2);
    // 6: compressed attention + selection (f32x2)
    cmp_attn_kernel<<<dim3(NSEQ, KVH), 256>>>(mem_kv);
    // 7: fine + slide (f32x2 QK + AV)
    fine_slide_kernel<<<dim3(NSEQ, KVH, 2), 256>>>();
    // 8: combine
    combine_kernel<<<dim3(NSEQ, NHEADS), 128>>>(bg);
    // 9: out = O1 @ W_out (plain TF32)
    gemm_tc<false><<<dim3(XDIM/64, NSEQ/128), 256, 49152>>>(
        p_AOh, nullptr, p_BFo, nullptr, out, 64, XDIM, XDIM, 0);
}